// round 14
// baseline (speedup 1.0000x reference)
#include <cuda_runtime.h>
#include <cuda_bf16.h>
#include <cstdint>
#include <cstddef>

#define NN 100000
#define EE 1600000
#define GG 128
#define HH 128
#define WALKN 16
#define PEDN 16
#define LL 5
#define OUTN 10

#define SWZ(o) ((o) ^ (((o) >> 3) & 0x70))

// ------------------- scratch (device globals: no allocs allowed) -------------------
__device__ __align__(16) float g_h[NN * HH];
__device__ __align__(16) float g_z[NN * HH];
__device__ __align__(16) __nv_bfloat16 g_ah[NN * 128];
__device__ __align__(16) __nv_bfloat16 g_al[NN * 128];
__device__ __align__(16) __nv_bfloat16 g_bh[NN * 256];
__device__ __align__(16) __nv_bfloat16 g_bl[NN * 256];
__device__ __align__(16) __nv_bfloat16 g_wh[5 * 98304];
__device__ __align__(16) __nv_bfloat16 g_wl[5 * 98304];
__device__ float g_rw[WALKN * NN];
__device__ float g_p[NN];
__device__ float g_q0[NN];
__device__ float g_q1[NN];
__device__ float g_dinv[NN];
__device__ float g_deg[NN];
__device__ float g_cnt[GG];
__device__ float g_pe[NN * PEDN];
__device__ float g_base[HH];
__device__ float g_cs[HH];
__device__ float g_cq[HH];
__device__ float g_mu[HH];
__device__ float g_rs[HH];
__device__ float g_gsum[GG * HH];
__device__ int   g_edge[2 * EE];
__device__ int   g_batch[NN];
__device__ int   g_flag[1];
// CSR (by destination col)
__device__ int   g_ideg[NN];
__device__ int   g_ptr[NN + 1];
__device__ int   g_fill[NN];
__device__ int   g_aux[512];
__device__ int   g_crow[EE];

// ------------------- dtype detection / conversion -------------------
__global__ void k_detect(const int* __restrict__ e, int* flag) {
    if (threadIdx.x == 0) {
        int nz = 0;
        for (int i = 0; i < 256; i++) nz |= e[2 * i + 1];
        flag[0] = (nz == 0) ? 1 : 0;
    }
}

__global__ void k_cvt(const void* __restrict__ src, int n, const int* __restrict__ flag,
                      int* __restrict__ dst) {
    int i = blockIdx.x * blockDim.x + threadIdx.x;
    if (i >= n) return;
    if (flag[0]) dst[i] = (int)((const long long*)src)[i];
    else         dst[i] = ((const int*)src)[i];
}

// ------------------- small kernels -------------------
__global__ void k_init(float* deg, float* cnt, int* ideg, float* cs, float* cq) {
    int i = blockIdx.x * blockDim.x + threadIdx.x;
    if (i < NN) { deg[i] = 1.0f; ideg[i] = 0; }
    if (i < GG) cnt[i] = 0.0f;
    if (i < HH) { cs[i] = 0.f; cq[i] = 0.f; }
}

__global__ void k_deg_scatter(const int* __restrict__ col, float* deg, int* ideg) {
    int e = blockIdx.x * blockDim.x + threadIdx.x;
    if (e < EE) {
        int c = col[e];
        atomicAdd(&deg[c], 1.0f);
        atomicAdd(&ideg[c], 1);
    }
}

// ---- prefix sum over ideg -> ptr (exclusive) ----
__global__ void k_scanA(const int* __restrict__ ideg, int* ptr, int* aux) {
    __shared__ int s[256];
    int i = blockIdx.x * 256 + threadIdx.x;
    int v = (i < NN) ? ideg[i] : 0;
    s[threadIdx.x] = v;
    __syncthreads();
    for (int off = 1; off < 256; off <<= 1) {
        int t = (threadIdx.x >= off) ? s[threadIdx.x - off] : 0;
        __syncthreads();
        s[threadIdx.x] += t;
        __syncthreads();
    }
    if (i < NN) ptr[i] = s[threadIdx.x] - v;
    if (threadIdx.x == 255) aux[blockIdx.x] = s[255];
}

__global__ void k_scanB(int* aux, int nb) {
    __shared__ int s[512];
    int v = (threadIdx.x < nb) ? aux[threadIdx.x] : 0;
    s[threadIdx.x] = v;
    __syncthreads();
    for (int off = 1; off < 512; off <<= 1) {
        int t = (threadIdx.x >= off) ? s[threadIdx.x - off] : 0;
        __syncthreads();
        s[threadIdx.x] += t;
        __syncthreads();
    }
    if (threadIdx.x < nb) aux[threadIdx.x] = s[threadIdx.x] - v;
}

__global__ void k_scanC(int* ptr, const int* __restrict__ aux, int* fill) {
    int i = blockIdx.x * blockDim.x + threadIdx.x;
    if (i < NN) {
        int v = ptr[i] + aux[i >> 8];
        ptr[i] = v;
        fill[i] = v;
    }
    if (i == 0) ptr[NN] = EE;
}

__global__ void k_csrfill(const int* __restrict__ row, const int* __restrict__ col,
                          int* fill, int* crow) {
    int e = blockIdx.x * blockDim.x + threadIdx.x;
    if (e >= EE) return;
    int pos = atomicAdd(&fill[col[e]], 1);
    crow[pos] = row[e];
}

__global__ void k_cnt_scatter(const int* __restrict__ batch, float* cnt) {
    int n = blockIdx.x * blockDim.x + threadIdx.x;
    if (n < NN) atomicAdd(&cnt[batch[n]], 1.0f);
}

__global__ void k_dinv(float* dinv, const float* __restrict__ deg) {
    int n = blockIdx.x * blockDim.x + threadIdx.x;
    if (n < NN) dinv[n] = rsqrtf(deg[n]);
}

// p0 = 1/cnt[batch]; q0 = p0 * dinv
__global__ void k_prob(const int* __restrict__ batch, const float* __restrict__ cnt,
                       const float* __restrict__ dinv, float* p, float* q) {
    int n = blockIdx.x * blockDim.x + threadIdx.x;
    if (n < NN) {
        float v = 1.0f / fmaxf(cnt[batch[n]], 1.0f);
        p[n] = v;
        q[n] = v * dinv[n];
    }
}

// fused RW step: rw[k]=p; p = 0.9*(dinv*(sum q_old[crow]) + p*dinv^2) + 0.1*p; q_new = p*dinv
__global__ void k_rwstep(const int* __restrict__ ptr, const int* __restrict__ crow,
                         const float* __restrict__ dinv,
                         float* __restrict__ p, const float* __restrict__ qold,
                         float* __restrict__ qnew, float* __restrict__ rwk, int do_update) {
    int n = blockIdx.x * blockDim.x + threadIdx.x;
    if (n >= NN) return;
    float pn = p[n];
    rwk[n] = pn;
    if (!do_update) return;
    int e0 = __ldg(ptr + n), e1 = __ldg(ptr + n + 1);
    float s = 0.f;
    int e = e0;
    for (; e + 4 <= e1; e += 4) {
        int r0 = __ldg(crow + e), r1 = __ldg(crow + e + 1);
        int r2 = __ldg(crow + e + 2), r3 = __ldg(crow + e + 3);
        s += __ldg(qold + r0) + __ldg(qold + r1) + __ldg(qold + r2) + __ldg(qold + r3);
    }
    for (; e < e1; e++) s += __ldg(qold + __ldg(crow + e));
    float d = dinv[n];
    float pnew = 0.9f * (d * s + pn * d * d) + 0.1f * pn;
    p[n] = pnew;
    qnew[n] = pnew * d;
}

__global__ void k_pe(const float* __restrict__ rw, const float* __restrict__ pe_w,
                     const float* __restrict__ pe_b, float* pe) {
    __shared__ float sw[WALKN * PEDN];
    __shared__ float sb[PEDN];
    if (threadIdx.x < WALKN * PEDN) sw[threadIdx.x] = pe_w[threadIdx.x];
    if (threadIdx.x < PEDN) sb[threadIdx.x] = pe_b[threadIdx.x];
    __syncthreads();
    int n = blockIdx.x * blockDim.x + threadIdx.x;
    if (n >= NN) return;
    float acc[PEDN];
#pragma unroll
    for (int j = 0; j < PEDN; j++) acc[j] = sb[j];
#pragma unroll
    for (int k = 0; k < WALKN; k++) {
        float r = rw[k * NN + n];
#pragma unroll
        for (int j = 0; j < PEDN; j++) acc[j] += r * sw[k * PEDN + j];
    }
#pragma unroll
    for (int j = 0; j < PEDN; j++) pe[n * PEDN + j] = acc[j];
}

__global__ void k_base(const float* __restrict__ emb, const float* __restrict__ proj_w,
                       const float* __restrict__ proj_b, float* base) {
    int o = threadIdx.x;
    float s = proj_b[o];
#pragma unroll 8
    for (int d = 0; d < 128; d++) s += emb[d] * proj_w[d * HH + o];
    base[o] = s;
}

__global__ void k_h0(const float* __restrict__ pe, const float* __restrict__ proj_w,
                     const float* __restrict__ base, float* h) {
    int idx = blockIdx.x * blockDim.x + threadIdx.x;
    if (idx >= NN * HH) return;
    int n = idx >> 7;
    int o = idx & 127;
    float s = base[o];
    const float* pw = proj_w + 128 * HH;
#pragma unroll
    for (int j = 0; j < PEDN; j++) s += pe[n * PEDN + j] * pw[j * HH + o];
    h[idx] = s;
}

// ------------------- CSR gather + fused bf16 split (agg = h[n] + sum_in h[r]) -------------------
__device__ __forceinline__ uint32_t bf2pack(float a, float b) {
    __nv_bfloat162 v = __halves2bfloat162(__float2bfloat16(a), __float2bfloat16(b));
    return *(uint32_t*)&v;
}

__global__ void __launch_bounds__(256)
k_gather(const int* __restrict__ ptr, const int* __restrict__ crow,
         const float* __restrict__ h,
         __nv_bfloat16* __restrict__ ah, __nv_bfloat16* __restrict__ al) {
    int w = (blockIdx.x * blockDim.x + threadIdx.x) >> 5;
    if (w >= NN) return;
    int lane = threadIdx.x & 31;
    float4 acc = __ldg((const float4*)(h + (size_t)w * HH) + lane);
    int e0 = __ldg(ptr + w), e1 = __ldg(ptr + w + 1);
    int e = e0;
    for (; e + 4 <= e1; e += 4) {
        int r0 = __ldg(crow + e), r1 = __ldg(crow + e + 1);
        int r2 = __ldg(crow + e + 2), r3 = __ldg(crow + e + 3);
        float4 v0 = __ldg((const float4*)(h + (size_t)r0 * HH) + lane);
        float4 v1 = __ldg((const float4*)(h + (size_t)r1 * HH) + lane);
        float4 v2 = __ldg((const float4*)(h + (size_t)r2 * HH) + lane);
        float4 v3 = __ldg((const float4*)(h + (size_t)r3 * HH) + lane);
        acc.x += v0.x + v1.x + v2.x + v3.x;
        acc.y += v0.y + v1.y + v2.y + v3.y;
        acc.z += v0.z + v1.z + v2.z + v3.z;
        acc.w += v0.w + v1.w + v2.w + v3.w;
    }
    for (; e < e1; e++) {
        int r = __ldg(crow + e);
        float4 v = __ldg((const float4*)(h + (size_t)r * HH) + lane);
        acc.x += v.x; acc.y += v.y; acc.z += v.z; acc.w += v.w;
    }
    float hx = __bfloat162float(__float2bfloat16(acc.x));
    float hy = __bfloat162float(__float2bfloat16(acc.y));
    float hz = __bfloat162float(__float2bfloat16(acc.z));
    float hw = __bfloat162float(__float2bfloat16(acc.w));
    uint2 hi, lo;
    hi.x = bf2pack(acc.x, acc.y);
    hi.y = bf2pack(acc.z, acc.w);
    lo.x = bf2pack(acc.x - hx, acc.y - hy);
    lo.y = bf2pack(acc.z - hz, acc.w - hw);
    *(uint2*)(ah + (size_t)w * HH + lane * 4) = hi;
    *(uint2*)(al + (size_t)w * HH + lane * 4) = lo;
}

// split + transpose ALL layer weights into [NO][K] bf16 hi/lo
__global__ void k_wsplit_all(const float* __restrict__ g1, const float* __restrict__ g2,
                             const float* __restrict__ f1, const float* __restrict__ f2,
                             __nv_bfloat16* __restrict__ wh, __nv_bfloat16* __restrict__ wl) {
    int idx = blockIdx.x * blockDim.x + threadIdx.x;
    if (idx >= 5 * 98304) return;
    int layer = idx / 98304, r = idx % 98304;
    const float* W; int Kd, NOd, base;
    if (r < 16384)      { W = g1 + layer * 16384; Kd = 128; NOd = 128; base = layer * 98304; }
    else if (r < 32768) { W = g2 + layer * 16384; r -= 16384; Kd = 128; NOd = 128; base = layer * 98304 + 16384; }
    else if (r < 65536) { W = f1 + layer * 32768; r -= 32768; Kd = 128; NOd = 256; base = layer * 98304 + 32768; }
    else                { W = f2 + layer * 32768; r -= 65536; Kd = 256; NOd = 128; base = layer * 98304 + 65536; }
    int k = r / NOd, n = r % NOd;
    float x = W[r];
    __nv_bfloat16 h = __float2bfloat16(x);
    wh[base + n * Kd + k] = h;
    wl[base + n * Kd + k] = __float2bfloat16(x - __bfloat162float(h));
}

// ------------------- bf16x3 tensor-core GEMM -------------------
__device__ __forceinline__ void ldsm4(uint32_t* r, uint32_t addr) {
    asm volatile("ldmatrix.sync.aligned.m8n8.x4.shared.b16 {%0,%1,%2,%3}, [%4];"
                 : "=r"(r[0]), "=r"(r[1]), "=r"(r[2]), "=r"(r[3]) : "r"(addr));
}

__device__ __forceinline__ void mma16816(float* c, const uint32_t* a, const uint32_t* b) {
    asm volatile("mma.sync.aligned.m16n8k16.row.col.f32.bf16.bf16.f32 "
                 "{%0,%1,%2,%3}, {%4,%5,%6,%7}, {%8,%9}, {%0,%1,%2,%3};"
                 : "+f"(c[0]), "+f"(c[1]), "+f"(c[2]), "+f"(c[3])
                 : "r"(a[0]), "r"(a[1]), "r"(a[2]), "r"(a[3]), "r"(b[0]), "r"(b[1]));
}

__device__ __forceinline__ void cpa16(uint32_t dst, const void* src) {
    asm volatile("cp.async.cg.shared.global [%0], [%1], 16;" :: "r"(dst), "l"(src));
}

// C = A @ W via split bf16 (AhWh + AlWh + AhWl), fp32 accum. Wh/Wl transposed [NO][K].
// OBF: write bf16 hi/lo outputs. STATS: accumulate per-column sum/sumsq into cs/cq.
template <int K, int NO, bool RELU, bool ADDRES, bool OBF, bool STATS>
__global__ void __launch_bounds__(256)
k_gemmT(const __nv_bfloat16* __restrict__ Ah, const __nv_bfloat16* __restrict__ Al,
        const __nv_bfloat16* __restrict__ Wh, const __nv_bfloat16* __restrict__ Wl,
        const float* __restrict__ bias, const float* __restrict__ res,
        float* __restrict__ Cf, __nv_bfloat16* __restrict__ Ch, __nv_bfloat16* __restrict__ Cl,
        float* __restrict__ cs, float* __restrict__ cq, int M) {
    constexpr int BK = 64;
    constexpr int KS = K / BK;
    extern __shared__ __align__(16) unsigned char smem[];   // 2 stages x 4 arrays x 16KB
    __shared__ float sS[128], sQ[128];
    uint32_t sb = (uint32_t)__cvta_generic_to_shared(smem);

    const int tid = threadIdx.x;
    const int m0 = blockIdx.x * 128;
    const int n0 = blockIdx.y * 128;
    const int warp = tid >> 5, lane = tid & 31;
    const int wm = warp >> 1, wn = warp & 1;   // 4 m-warps x 2 n-warps

    if (STATS) {
        if (tid < 128) { sS[tid] = 0.f; sQ[tid] = 0.f; }
    }

    auto issue_stage = [&](int s) {
        int stage = s & 1;
        int kb = s * BK;
#pragma unroll
        for (int a = 0; a < 4; a++) {
            const __nv_bfloat16* S = (a == 0) ? Ah : (a == 1) ? Al : (a == 2) ? Wh : Wl;
#pragma unroll
            for (int j = 0; j < 4; j++) {
                int chunk = tid + j * 256;
                int row = chunk >> 3, cq8 = chunk & 7;
                uint32_t off = (uint32_t)(stage * 65536 + a * 16384 + SWZ(row * 128 + cq8 * 16));
                if (a < 2) {
                    int m = m0 + row;
                    if (m < M) cpa16(sb + off, S + (size_t)m * K + kb + cq8 * 8);
                    else { uint4 zz = make_uint4(0, 0, 0, 0); *(uint4*)(smem + off) = zz; }
                } else {
                    cpa16(sb + off, S + (size_t)(n0 + row) * K + kb + cq8 * 8);
                }
            }
        }
        asm volatile("cp.async.commit_group;");
    };

    float c[2][8][4];
#pragma unroll
    for (int mi = 0; mi < 2; mi++)
#pragma unroll
        for (int nb = 0; nb < 8; nb++)
#pragma unroll
            for (int q = 0; q < 4; q++) c[mi][nb][q] = 0.f;

    issue_stage(0);

    const int id = lane >> 3, r8 = lane & 7;
#pragma unroll 1
    for (int s = 0; s < KS; s++) {
        if (s + 1 < KS) {
            issue_stage(s + 1);
            asm volatile("cp.async.wait_group 1;");
        } else {
            asm volatile("cp.async.wait_group 0;");
        }
        __syncthreads();

        uint32_t sbase = sb + (uint32_t)((s & 1) * 65536);
#pragma unroll
        for (int kk = 0; kk < 4; kk++) {
            uint32_t ah_[2][4], al_[2][4];
#pragma unroll
            for (int mi = 0; mi < 2; mi++) {
                int mrow = wm * 32 + mi * 16 + (id & 1) * 8 + r8;
                uint32_t off = (uint32_t)SWZ(mrow * 128 + kk * 32 + (id >> 1) * 16);
                ldsm4(ah_[mi], sbase + off);
                ldsm4(al_[mi], sbase + 16384 + off);
            }
#pragma unroll
            for (int np = 0; np < 4; np++) {
                int nrow = wn * 64 + np * 16 + (id >> 1) * 8 + r8;
                uint32_t woff = (uint32_t)SWZ(nrow * 128 + kk * 32 + (id & 1) * 16);
                uint32_t wh_[4], wl_[4];
                ldsm4(wh_, sbase + 32768 + woff);
                ldsm4(wl_, sbase + 49152 + woff);
#pragma unroll
                for (int mi = 0; mi < 2; mi++) {
                    mma16816(c[mi][np * 2],     ah_[mi], wh_);
                    mma16816(c[mi][np * 2 + 1], ah_[mi], wh_ + 2);
                    mma16816(c[mi][np * 2],     al_[mi], wh_);
                    mma16816(c[mi][np * 2 + 1], al_[mi], wh_ + 2);
                    mma16816(c[mi][np * 2],     ah_[mi], wl_);
                    mma16816(c[mi][np * 2 + 1], ah_[mi], wl_ + 2);
                }
            }
        }
        __syncthreads();
    }

    // ---- epilogue ----
#pragma unroll
    for (int nb = 0; nb < 8; nb++) {
        int col = n0 + wn * 64 + nb * 8 + (lane & 3) * 2;
        float b0 = bias[col], b1 = bias[col + 1];
        float ls0 = 0.f, lq0 = 0.f, ls1 = 0.f, lq1 = 0.f;
#pragma unroll
        for (int mi = 0; mi < 2; mi++) {
            int r0 = m0 + wm * 32 + mi * 16 + (lane >> 2);
            float* cc = c[mi][nb];
#pragma unroll
            for (int half = 0; half < 2; half++) {
                int r = r0 + half * 8;
                if (r >= M) continue;
                float o0 = cc[2 * half] + b0, o1 = cc[2 * half + 1] + b1;
                if (RELU) { o0 = fmaxf(o0, 0.f); o1 = fmaxf(o1, 0.f); }
                if (ADDRES) {
                    float2 rv = *(const float2*)(res + (size_t)r * NO + col);
                    o0 += rv.x; o1 += rv.y;
                }
                if (OBF) {
                    float h0 = __bfloat162float(__float2bfloat16(o0));
                    float h1 = __bfloat162float(__float2bfloat16(o1));
                    *(uint32_t*)(Ch + (size_t)r * NO + col) = bf2pack(o0, o1);
                    *(uint32_t*)(Cl + (size_t)r * NO + col) = bf2pack(o0 - h0, o1 - h1);
                } else {
                    *(float2*)(Cf + (size_t)r * NO + col) = make_float2(o0, o1);
                }
                if (STATS) {
                    ls0 += o0; lq0 += o0 * o0;
                    ls1 += o1; lq1 += o1 * o1;
                }
            }
        }
        if (STATS) {
            int lc = col - n0;
            atomicAdd(&sS[lc], ls0);
            atomicAdd(&sQ[lc], lq0);
            atomicAdd(&sS[lc + 1], ls1);
            atomicAdd(&sQ[lc + 1], lq1);
        }
    }
    if (STATS) {
        __syncthreads();
        if (tid < 128) {
            atomicAdd(&cs[n0 + tid], sS[tid]);
            atomicAdd(&cq[n0 + tid], sQ[tid]);
        }
    }
}

static constexpr int SM_T = 131072;   // 2 stages x 4 arrays x 16KB

// ------------------- batchnorm pieces -------------------
// compute mu/rs and re-zero cs/cq for the next stats pass
__global__ void k_murs(float* cs, float* cq, float* mu, float* rs) {
    int c = threadIdx.x;
    float m = cs[c] * (1.0f / NN);
    mu[c] = m;
    float v = cq[c] * (1.0f / NN) - m * m;
    rs[c] = rsqrtf(v + 1e-5f);
    cs[c] = 0.f;
    cq[c] = 0.f;
}

// h += relu(bn(z));  also emit bf16 hi/lo of new h
__global__ void k_bn_relu_res_split(const float* __restrict__ z, const float* __restrict__ mu,
                                    const float* __restrict__ rs, const float* __restrict__ g,
                                    const float* __restrict__ b, float* __restrict__ h,
                                    __nv_bfloat16* __restrict__ ah, __nv_bfloat16* __restrict__ al) {
    int idx = blockIdx.x * blockDim.x + threadIdx.x;    // over NN*32 float4s
    if (idx >= NN * 32) return;
    int n = idx >> 5, c4 = (idx & 31) * 4;
    float4 z4 = *(const float4*)(z + (size_t)n * HH + c4);
    float4 h4 = *(const float4*)(h + (size_t)n * HH + c4);
    float o0 = h4.x + fmaxf((z4.x - mu[c4]) * rs[c4] * g[c4] + b[c4], 0.f);
    float o1 = h4.y + fmaxf((z4.y - mu[c4 + 1]) * rs[c4 + 1] * g[c4 + 1] + b[c4 + 1], 0.f);
    float o2 = h4.z + fmaxf((z4.z - mu[c4 + 2]) * rs[c4 + 2] * g[c4 + 2] + b[c4 + 2], 0.f);
    float o3 = h4.w + fmaxf((z4.w - mu[c4 + 3]) * rs[c4 + 3] * g[c4 + 3] + b[c4 + 3], 0.f);
    *(float4*)(h + (size_t)n * HH + c4) = make_float4(o0, o1, o2, o3);
    float p0 = __bfloat162float(__float2bfloat16(o0));
    float p1 = __bfloat162float(__float2bfloat16(o1));
    float p2 = __bfloat162float(__float2bfloat16(o2));
    float p3 = __bfloat162float(__float2bfloat16(o3));
    uint2 hi, lo;
    hi.x = bf2pack(o0, o1); hi.y = bf2pack(o2, o3);
    lo.x = bf2pack(o0 - p0, o1 - p1); lo.y = bf2pack(o2 - p2, o3 - p3);
    *(uint2*)(ah + (size_t)n * HH + c4) = hi;
    *(uint2*)(al + (size_t)n * HH + c4) = lo;
}

__global__ void k_bn(const float* __restrict__ z, const float* __restrict__ mu,
                     const float* __restrict__ rs, const float* __restrict__ g,
                     const float* __restrict__ b, float* h) {
    int idx = blockIdx.x * blockDim.x + threadIdx.x;
    if (idx >= NN * HH) return;
    int c = idx & 127;
    h[idx] = (z[idx] - mu[c]) * rs[c] * g[c] + b[c];
}

// ------------------- pooling + head -------------------
__global__ void k_zero_gsum(float* gs) {
    int i = blockIdx.x * blockDim.x + threadIdx.x;
    if (i < GG * HH) gs[i] = 0.f;
}

__global__ void k_pool(const float* __restrict__ h, const int* __restrict__ batch,
                       float* gsum) {
    int c = threadIdx.x;
    int R = (NN + gridDim.x - 1) / gridDim.x;
    int n0 = blockIdx.x * R;
    int n1 = min(n0 + R, NN);
    if (n0 >= n1) return;
    float acc = 0.f;
    int cg = batch[n0];
    for (int n = n0; n < n1; n++) {
        int g = batch[n];
        if (g != cg) {
            atomicAdd(&gsum[cg * HH + c], acc);
            acc = 0.f;
            cg = g;
        }
        acc += h[(size_t)n * HH + c];
    }
    atomicAdd(&gsum[cg * HH + c], acc);
}

__global__ void k_head(const float* __restrict__ gsum, const float* __restrict__ cnt,
                       const float* __restrict__ w1, const float* __restrict__ b1,
                       const float* __restrict__ w2, const float* __restrict__ b2,
                       float* out) {
    __shared__ float gv[HH];
    __shared__ float hid[HH];
    int t = threadIdx.x;
    int gI = blockIdx.x;
    gv[t] = gsum[gI * HH + t] / fmaxf(cnt[gI], 1.0f);
    __syncthreads();
    float s = b1[t];
#pragma unroll 8
    for (int k = 0; k < HH; k++) s += gv[k] * w1[k * HH + t];
    hid[t] = fmaxf(s, 0.f);
    __syncthreads();
    if (t < OUTN) {
        float o = b2[t];
#pragma unroll 8
        for (int k = 0; k < HH; k++) o += hid[k] * w2[k * OUTN + t];
        out[gI * OUTN + t] = o;
    }
}

// ------------------- launcher -------------------
static inline int cdiv(long a, long b) { return (int)((a + b - 1) / b); }

extern "C" void kernel_launch(void* const* d_in, const int* in_sizes, int n_in,
                              void* d_out, int out_size) {
    const void *edge_raw, *batch_raw;
    const float *emb, *pe_w, *pe_b, *proj_w, *proj_b;
    const float *gin_w1, *gin_b1, *gin_w2, *gin_b2, *bn_g, *bn_b;
    const float *ffn_w1, *ffn_b1, *ffn_w2, *ffn_b2, *fbn_g, *fbn_b;
    const float *ow1, *ob1, *ow2, *ob2;

    if (in_sizes[1] == 2 * EE) {
        edge_raw  = d_in[1];  batch_raw = d_in[2];
        emb  = (const float*)d_in[3];  pe_w = (const float*)d_in[4];  pe_b = (const float*)d_in[5];
        proj_w = (const float*)d_in[6]; proj_b = (const float*)d_in[7];
        gin_w1 = (const float*)d_in[8]; gin_b1 = (const float*)d_in[9];
        gin_w2 = (const float*)d_in[10]; gin_b2 = (const float*)d_in[11];
        bn_g = (const float*)d_in[12]; bn_b = (const float*)d_in[13];
        ffn_w1 = (const float*)d_in[14]; ffn_b1 = (const float*)d_in[15];
        ffn_w2 = (const float*)d_in[16]; ffn_b2 = (const float*)d_in[17];
        fbn_g = (const float*)d_in[18]; fbn_b = (const float*)d_in[19];
        ow1 = (const float*)d_in[20]; ob1 = (const float*)d_in[21];
        ow2 = (const float*)d_in[22]; ob2 = (const float*)d_in[23];
    } else {
        batch_raw = d_in[0];
        bn_b = (const float*)d_in[1]; bn_g = (const float*)d_in[2];
        edge_raw = d_in[3];
        emb = (const float*)d_in[4];
        ffn_b1 = (const float*)d_in[5]; ffn_b2 = (const float*)d_in[6];
        fbn_b = (const float*)d_in[7]; fbn_g = (const float*)d_in[8];
        ffn_w1 = (const float*)d_in[9]; ffn_w2 = (const float*)d_in[10];
        gin_b1 = (const float*)d_in[11]; gin_b2 = (const float*)d_in[12];
        gin_w1 = (const float*)d_in[13]; gin_w2 = (const float*)d_in[14];
        ob1 = (const float*)d_in[15]; ob2 = (const float*)d_in[16];
        ow1 = (const float*)d_in[17]; ow2 = (const float*)d_in[18];
        pe_b = (const float*)d_in[19]; pe_w = (const float*)d_in[20];
        proj_b = (const float*)d_in[21]; proj_w = (const float*)d_in[22];
    }
    float* out = (float*)d_out;

    float *h, *z, *rw, *p, *q0, *q1, *dinv, *deg, *cnt, *pe, *base;
    float *cs, *cq, *mu, *rs, *gsum;
    int *edge, *batch, *flag, *ideg, *ptr, *fill, *aux, *crow;
    __nv_bfloat16 *ah, *al, *bh, *bl, *wh, *wl;
    cudaGetSymbolAddress((void**)&h, g_h);
    cudaGetSymbolAddress((void**)&z, g_z);
    cudaGetSymbolAddress((void**)&rw, g_rw);
    cudaGetSymbolAddress((void**)&p, g_p);
    cudaGetSymbolAddress((void**)&q0, g_q0);
    cudaGetSymbolAddress((void**)&q1, g_q1);
    cudaGetSymbolAddress((void**)&dinv, g_dinv);
    cudaGetSymbolAddress((void**)&deg, g_deg);
    cudaGetSymbolAddress((void**)&cnt, g_cnt);
    cudaGetSymbolAddress((void**)&pe, g_pe);
    cudaGetSymbolAddress((void**)&base, g_base);
    cudaGetSymbolAddress((void**)&cs, g_cs);
    cudaGetSymbolAddress((void**)&cq, g_cq);
    cudaGetSymbolAddress((void**)&mu, g_mu);
    cudaGetSymbolAddress((void**)&rs, g_rs);
    cudaGetSymbolAddress((void**)&gsum, g_gsum);
    cudaGetSymbolAddress((void**)&edge, g_edge);
    cudaGetSymbolAddress((void**)&batch, g_batch);
    cudaGetSymbolAddress((void**)&flag, g_flag);
    cudaGetSymbolAddress((void**)&ideg, g_ideg);
    cudaGetSymbolAddress((void**)&ptr, g_ptr);
    cudaGetSymbolAddress((void**)&fill, g_fill);
    cudaGetSymbolAddress((void**)&aux, g_aux);
    cudaGetSymbolAddress((void**)&crow, g_crow);
    cudaGetSymbolAddress((void**)&ah, g_ah);
    cudaGetSymbolAddress((void**)&al, g_al);
    cudaGetSymbolAddress((void**)&bh, g_bh);
    cudaGetSymbolAddress((void**)&bl, g_bl);
    cudaGetSymbolAddress((void**)&wh, g_wh);
    cudaGetSymbolAddress((void**)&wl, g_wl);

    const int NT = 256;

    k_detect<<<1, 32>>>((const int*)edge_raw, flag);
    k_cvt<<<cdiv(2 * (long)EE, NT), NT>>>(edge_raw, 2 * EE, flag, edge);
    k_cvt<<<cdiv(NN, NT), NT>>>(batch_raw, NN, flag, batch);
    const int* row0 = edge;
    const int* col0 = edge + EE;

    cudaFuncSetAttribute(k_gemmT<128, 128, true,  false, true,  false>, cudaFuncAttributeMaxDynamicSharedMemorySize, SM_T);
    cudaFuncSetAttribute(k_gemmT<128, 128, false, false, false, true >, cudaFuncAttributeMaxDynamicSharedMemorySize, SM_T);
    cudaFuncSetAttribute(k_gemmT<128, 256, true,  false, true,  false>, cudaFuncAttributeMaxDynamicSharedMemorySize, SM_T);
    cudaFuncSetAttribute(k_gemmT<256, 128, false, true,  false, true >, cudaFuncAttributeMaxDynamicSharedMemorySize, SM_T);

    // split + transpose all layer weights (once)
    k_wsplit_all<<<cdiv(5 * 98304, NT), NT>>>(gin_w1, gin_w2, ffn_w1, ffn_w2, wh, wl);

    // degrees / CSR / counts
    k_init<<<cdiv(NN, NT), NT>>>(deg, cnt, ideg, cs, cq);
    k_deg_scatter<<<cdiv(EE, NT), NT>>>(col0, deg, ideg);
    const int NB = cdiv(NN, 256);   // 391
    k_scanA<<<NB, 256>>>(ideg, ptr, aux);
    k_scanB<<<1, 512>>>(aux, NB);
    k_scanC<<<NB, 256>>>(ptr, aux, fill);
    k_csrfill<<<cdiv(EE, NT), NT>>>(row0, col0, fill, crow);
    k_cnt_scatter<<<cdiv(NN, NT), NT>>>(batch, cnt);
    k_dinv<<<cdiv(NN, NT), NT>>>(dinv, deg);
    k_prob<<<cdiv(NN, NT), NT>>>(batch, cnt, dinv, p, q0);

    // random walk PE — fused CSR-gather step (no atomics)
    {
        float *qa = q0, *qb = q1;
        for (int k = 0; k < WALKN; k++) {
            k_rwstep<<<cdiv(NN, NT), NT>>>(ptr, crow, dinv, p, qa, qb, rw + (long)k * NN,
                                           (k < WALKN - 1) ? 1 : 0);
            float* tw = qa; qa = qb; qb = tw;
        }
    }
    k_pe<<<cdiv(NN, 256), 256>>>(rw, pe_w, pe_b, pe);

    k_base<<<1, HH>>>(emb, proj_w, proj_b, base);
    k_h0<<<cdiv((long)NN * HH, NT), NT>>>(pe, proj_w, base, h);

    const int MT = cdiv(NN, 128);            // 782 m-tiles
    const int GW = cdiv((long)NN * 32, NT);  // gather grid
    const int B4 = cdiv((long)NN * 32, NT);  // bn split grid (float4 units)
    for (int i = 0; i < LL; i++) {
        const __nv_bfloat16* whL = wh + i * 98304;
        const __nv_bfloat16* wlL = wl + i * 98304;
        k_gather<<<GW, NT>>>(ptr, crow, h, ah, al);
        k_gemmT<128, 128, true,  false, true,  false><<<dim3(MT, 1), 256, SM_T>>>(ah, al, whL, wlL, gin_b1 + i * HH, nullptr, nullptr, bh, bl, nullptr, nullptr, NN);
        k_gemmT<128, 128, false, false, false, true ><<<dim3(MT, 1), 256, SM_T>>>(bh, bl, whL + 16384, wlL + 16384, gin_b2 + i * HH, nullptr, z, nullptr, nullptr, cs, cq, NN);
        k_murs<<<1, HH>>>(cs, cq, mu, rs);
        k_bn_relu_res_split<<<B4, NT>>>(z, mu, rs, bn_g + i * HH, bn_b + i * HH, h, ah, al);

        k_gemmT<128, 256, true,  false, true,  false><<<dim3(MT, 2), 256, SM_T>>>(ah, al, whL + 32768, wlL + 32768, ffn_b1 + i * 2 * HH, nullptr, nullptr, bh, bl, nullptr, nullptr, NN);
        k_gemmT<256, 128, false, true,  false, true ><<<dim3(MT, 1), 256, SM_T>>>(bh, bl, whL + 65536, wlL + 65536, ffn_b2 + i * HH, h, z, nullptr, nullptr, cs, cq, NN);
        k_murs<<<1, HH>>>(cs, cq, mu, rs);
        k_bn<<<cdiv(NN * HH, NT), NT>>>(z, mu, rs, fbn_g + i * HH, fbn_b + i * HH, h);
    }

    k_zero_gsum<<<cdiv(GG * HH, NT), NT>>>(gsum);
    k_pool<<<512, HH>>>(h, batch, gsum);
    k_head<<<GG, HH>>>(gsum, cnt, ow1, ob1, ow2, ob2, out);
}

// round 15
// speedup vs baseline: 1.1480x; 1.1480x over previous
#include <cuda_runtime.h>
#include <cuda_bf16.h>
#include <cstdint>
#include <cstddef>

#define NN 100000
#define EE 1600000
#define GG 128
#define HH 128
#define WALKN 16
#define PEDN 16
#define LL 5
#define OUTN 10

#define SWZ(o) ((o) ^ (((o) >> 3) & 0x70))

// ------------------- scratch (device globals: no allocs allowed) -------------------
__device__ __align__(16) float g_h[NN * HH];
__device__ __align__(16) float g_z[NN * HH];
__device__ __align__(16) __nv_bfloat16 g_ah[NN * 128];
__device__ __align__(16) __nv_bfloat16 g_al[NN * 128];
__device__ __align__(16) __nv_bfloat16 g_bh[NN * 256];
__device__ __align__(16) __nv_bfloat16 g_bl[NN * 256];
__device__ __align__(16) __nv_bfloat16 g_wh[5 * 98304];
__device__ __align__(16) __nv_bfloat16 g_wl[5 * 98304];
__device__ float g_rw[WALKN * NN];
__device__ float g_p[NN];
__device__ float g_q0[NN];
__device__ float g_q1[NN];
__device__ float g_dinv[NN];
__device__ float g_deg[NN];
__device__ float g_cnt[GG];
__device__ float g_pe[NN * PEDN];
__device__ float g_base[HH];
__device__ float g_cs[HH];
__device__ float g_cq[HH];
__device__ float g_mu[HH];
__device__ float g_rs[HH];
__device__ float g_gsum[GG * HH];
__device__ int   g_edge[2 * EE];
__device__ int   g_batch[NN];
__device__ int   g_flag[1];
// CSR (by destination col)
__device__ int   g_ideg[NN];
__device__ int   g_ptr[NN + 1];
__device__ int   g_fill[NN];
__device__ int   g_aux[512];
__device__ int   g_crow[EE];

// ------------------- dtype detection / conversion -------------------
__global__ void k_detect(const int* __restrict__ e, int* flag) {
    if (threadIdx.x == 0) {
        int nz = 0;
        for (int i = 0; i < 256; i++) nz |= e[2 * i + 1];
        flag[0] = (nz == 0) ? 1 : 0;
    }
}

__global__ void k_cvt(const void* __restrict__ src, int n, const int* __restrict__ flag,
                      int* __restrict__ dst) {
    int i = blockIdx.x * blockDim.x + threadIdx.x;
    if (i >= n) return;
    if (flag[0]) dst[i] = (int)((const long long*)src)[i];
    else         dst[i] = ((const int*)src)[i];
}

// ------------------- small kernels -------------------
__global__ void k_init(float* deg, float* cnt, int* ideg, float* cs, float* cq) {
    int i = blockIdx.x * blockDim.x + threadIdx.x;
    if (i < NN) { deg[i] = 1.0f; ideg[i] = 0; }
    if (i < GG) cnt[i] = 0.0f;
    if (i < HH) { cs[i] = 0.f; cq[i] = 0.f; }
}

__global__ void k_deg_scatter(const int* __restrict__ col, float* deg, int* ideg) {
    int e = blockIdx.x * blockDim.x + threadIdx.x;
    if (e < EE) {
        int c = col[e];
        atomicAdd(&deg[c], 1.0f);
        atomicAdd(&ideg[c], 1);
    }
}

// ---- prefix sum over ideg -> ptr (exclusive) ----
__global__ void k_scanA(const int* __restrict__ ideg, int* ptr, int* aux) {
    __shared__ int s[256];
    int i = blockIdx.x * 256 + threadIdx.x;
    int v = (i < NN) ? ideg[i] : 0;
    s[threadIdx.x] = v;
    __syncthreads();
    for (int off = 1; off < 256; off <<= 1) {
        int t = (threadIdx.x >= off) ? s[threadIdx.x - off] : 0;
        __syncthreads();
        s[threadIdx.x] += t;
        __syncthreads();
    }
    if (i < NN) ptr[i] = s[threadIdx.x] - v;
    if (threadIdx.x == 255) aux[blockIdx.x] = s[255];
}

__global__ void k_scanB(int* aux, int nb) {
    __shared__ int s[512];
    int v = (threadIdx.x < nb) ? aux[threadIdx.x] : 0;
    s[threadIdx.x] = v;
    __syncthreads();
    for (int off = 1; off < 512; off <<= 1) {
        int t = (threadIdx.x >= off) ? s[threadIdx.x - off] : 0;
        __syncthreads();
        s[threadIdx.x] += t;
        __syncthreads();
    }
    if (threadIdx.x < nb) aux[threadIdx.x] = s[threadIdx.x] - v;
}

__global__ void k_scanC(int* ptr, const int* __restrict__ aux, int* fill) {
    int i = blockIdx.x * blockDim.x + threadIdx.x;
    if (i < NN) {
        int v = ptr[i] + aux[i >> 8];
        ptr[i] = v;
        fill[i] = v;
    }
    if (i == 0) ptr[NN] = EE;
}

__global__ void k_csrfill(const int* __restrict__ row, const int* __restrict__ col,
                          int* fill, int* crow) {
    int e = blockIdx.x * blockDim.x + threadIdx.x;
    if (e >= EE) return;
    int pos = atomicAdd(&fill[col[e]], 1);
    crow[pos] = row[e];
}

__global__ void k_cnt_scatter(const int* __restrict__ batch, float* cnt) {
    int n = blockIdx.x * blockDim.x + threadIdx.x;
    if (n < NN) atomicAdd(&cnt[batch[n]], 1.0f);
}

__global__ void k_dinv(float* dinv, const float* __restrict__ deg) {
    int n = blockIdx.x * blockDim.x + threadIdx.x;
    if (n < NN) dinv[n] = rsqrtf(deg[n]);
}

// p0 = 1/cnt[batch]; q0 = p0 * dinv
__global__ void k_prob(const int* __restrict__ batch, const float* __restrict__ cnt,
                       const float* __restrict__ dinv, float* p, float* q) {
    int n = blockIdx.x * blockDim.x + threadIdx.x;
    if (n < NN) {
        float v = 1.0f / fmaxf(cnt[batch[n]], 1.0f);
        p[n] = v;
        q[n] = v * dinv[n];
    }
}

// fused RW step: rw[k]=p; p = 0.9*(dinv*(sum q_old[crow]) + p*dinv^2) + 0.1*p; q_new = p*dinv
__global__ void k_rwstep(const int* __restrict__ ptr, const int* __restrict__ crow,
                         const float* __restrict__ dinv,
                         float* __restrict__ p, const float* __restrict__ qold,
                         float* __restrict__ qnew, float* __restrict__ rwk, int do_update) {
    int n = blockIdx.x * blockDim.x + threadIdx.x;
    if (n >= NN) return;
    float pn = p[n];
    rwk[n] = pn;
    if (!do_update) return;
    int e0 = __ldg(ptr + n), e1 = __ldg(ptr + n + 1);
    float s = 0.f;
    int e = e0;
    for (; e + 4 <= e1; e += 4) {
        int r0 = __ldg(crow + e), r1 = __ldg(crow + e + 1);
        int r2 = __ldg(crow + e + 2), r3 = __ldg(crow + e + 3);
        s += __ldg(qold + r0) + __ldg(qold + r1) + __ldg(qold + r2) + __ldg(qold + r3);
    }
    for (; e < e1; e++) s += __ldg(qold + __ldg(crow + e));
    float d = dinv[n];
    float pnew = 0.9f * (d * s + pn * d * d) + 0.1f * pn;
    p[n] = pnew;
    qnew[n] = pnew * d;
}

__global__ void k_pe(const float* __restrict__ rw, const float* __restrict__ pe_w,
                     const float* __restrict__ pe_b, float* pe) {
    __shared__ float sw[WALKN * PEDN];
    __shared__ float sb[PEDN];
    if (threadIdx.x < WALKN * PEDN) sw[threadIdx.x] = pe_w[threadIdx.x];
    if (threadIdx.x < PEDN) sb[threadIdx.x] = pe_b[threadIdx.x];
    __syncthreads();
    int n = blockIdx.x * blockDim.x + threadIdx.x;
    if (n >= NN) return;
    float acc[PEDN];
#pragma unroll
    for (int j = 0; j < PEDN; j++) acc[j] = sb[j];
#pragma unroll
    for (int k = 0; k < WALKN; k++) {
        float r = rw[k * NN + n];
#pragma unroll
        for (int j = 0; j < PEDN; j++) acc[j] += r * sw[k * PEDN + j];
    }
#pragma unroll
    for (int j = 0; j < PEDN; j++) pe[n * PEDN + j] = acc[j];
}

__global__ void k_base(const float* __restrict__ emb, const float* __restrict__ proj_w,
                       const float* __restrict__ proj_b, float* base) {
    int o = threadIdx.x;
    float s = proj_b[o];
#pragma unroll 8
    for (int d = 0; d < 128; d++) s += emb[d] * proj_w[d * HH + o];
    base[o] = s;
}

__global__ void k_h0(const float* __restrict__ pe, const float* __restrict__ proj_w,
                     const float* __restrict__ base, float* h) {
    int idx = blockIdx.x * blockDim.x + threadIdx.x;
    if (idx >= NN * HH) return;
    int n = idx >> 7;
    int o = idx & 127;
    float s = base[o];
    const float* pw = proj_w + 128 * HH;
#pragma unroll
    for (int j = 0; j < PEDN; j++) s += pe[n * PEDN + j] * pw[j * HH + o];
    h[idx] = s;
}

// ------------------- CSR gather + fused bf16 split (agg = h[n] + sum_in h[r]) -------------------
__device__ __forceinline__ uint32_t bf2pack(float a, float b) {
    __nv_bfloat162 v = __halves2bfloat162(__float2bfloat16(a), __float2bfloat16(b));
    return *(uint32_t*)&v;
}

__global__ void __launch_bounds__(256)
k_gather(const int* __restrict__ ptr, const int* __restrict__ crow,
         const float* __restrict__ h,
         __nv_bfloat16* __restrict__ ah, __nv_bfloat16* __restrict__ al) {
    int w = (blockIdx.x * blockDim.x + threadIdx.x) >> 5;
    if (w >= NN) return;
    int lane = threadIdx.x & 31;
    float4 acc = __ldg((const float4*)(h + (size_t)w * HH) + lane);
    int e0 = __ldg(ptr + w), e1 = __ldg(ptr + w + 1);
    int e = e0;
    for (; e + 4 <= e1; e += 4) {
        int r0 = __ldg(crow + e), r1 = __ldg(crow + e + 1);
        int r2 = __ldg(crow + e + 2), r3 = __ldg(crow + e + 3);
        float4 v0 = __ldg((const float4*)(h + (size_t)r0 * HH) + lane);
        float4 v1 = __ldg((const float4*)(h + (size_t)r1 * HH) + lane);
        float4 v2 = __ldg((const float4*)(h + (size_t)r2 * HH) + lane);
        float4 v3 = __ldg((const float4*)(h + (size_t)r3 * HH) + lane);
        acc.x += v0.x + v1.x + v2.x + v3.x;
        acc.y += v0.y + v1.y + v2.y + v3.y;
        acc.z += v0.z + v1.z + v2.z + v3.z;
        acc.w += v0.w + v1.w + v2.w + v3.w;
    }
    for (; e < e1; e++) {
        int r = __ldg(crow + e);
        float4 v = __ldg((const float4*)(h + (size_t)r * HH) + lane);
        acc.x += v.x; acc.y += v.y; acc.z += v.z; acc.w += v.w;
    }
    float hx = __bfloat162float(__float2bfloat16(acc.x));
    float hy = __bfloat162float(__float2bfloat16(acc.y));
    float hz = __bfloat162float(__float2bfloat16(acc.z));
    float hw = __bfloat162float(__float2bfloat16(acc.w));
    uint2 hi, lo;
    hi.x = bf2pack(acc.x, acc.y);
    hi.y = bf2pack(acc.z, acc.w);
    lo.x = bf2pack(acc.x - hx, acc.y - hy);
    lo.y = bf2pack(acc.z - hz, acc.w - hw);
    *(uint2*)(ah + (size_t)w * HH + lane * 4) = hi;
    *(uint2*)(al + (size_t)w * HH + lane * 4) = lo;
}

// split + transpose ALL layer weights into [NO][K] bf16 hi/lo
__global__ void k_wsplit_all(const float* __restrict__ g1, const float* __restrict__ g2,
                             const float* __restrict__ f1, const float* __restrict__ f2,
                             __nv_bfloat16* __restrict__ wh, __nv_bfloat16* __restrict__ wl) {
    int idx = blockIdx.x * blockDim.x + threadIdx.x;
    if (idx >= 5 * 98304) return;
    int layer = idx / 98304, r = idx % 98304;
    const float* W; int Kd, NOd, base;
    if (r < 16384)      { W = g1 + layer * 16384; Kd = 128; NOd = 128; base = layer * 98304; }
    else if (r < 32768) { W = g2 + layer * 16384; r -= 16384; Kd = 128; NOd = 128; base = layer * 98304 + 16384; }
    else if (r < 65536) { W = f1 + layer * 32768; r -= 32768; Kd = 128; NOd = 256; base = layer * 98304 + 32768; }
    else                { W = f2 + layer * 32768; r -= 65536; Kd = 256; NOd = 128; base = layer * 98304 + 65536; }
    int k = r / NOd, n = r % NOd;
    float x = W[r];
    __nv_bfloat16 h = __float2bfloat16(x);
    wh[base + n * Kd + k] = h;
    wl[base + n * Kd + k] = __float2bfloat16(x - __bfloat162float(h));
}

// ------------------- bf16x3 tensor-core GEMM -------------------
__device__ __forceinline__ void ldsm4(uint32_t* r, uint32_t addr) {
    asm volatile("ldmatrix.sync.aligned.m8n8.x4.shared.b16 {%0,%1,%2,%3}, [%4];"
                 : "=r"(r[0]), "=r"(r[1]), "=r"(r[2]), "=r"(r[3]) : "r"(addr));
}

__device__ __forceinline__ void mma16816(float* c, const uint32_t* a, const uint32_t* b) {
    asm volatile("mma.sync.aligned.m16n8k16.row.col.f32.bf16.bf16.f32 "
                 "{%0,%1,%2,%3}, {%4,%5,%6,%7}, {%8,%9}, {%0,%1,%2,%3};"
                 : "+f"(c[0]), "+f"(c[1]), "+f"(c[2]), "+f"(c[3])
                 : "r"(a[0]), "r"(a[1]), "r"(a[2]), "r"(a[3]), "r"(b[0]), "r"(b[1]));
}

__device__ __forceinline__ void cpa16(uint32_t dst, const void* src) {
    asm volatile("cp.async.cg.shared.global [%0], [%1], 16;" :: "r"(dst), "l"(src));
}

// C = A @ W via split bf16 (AhWh + AlWh + AhWl), fp32 accum. Wh/Wl transposed [NO][K].
// OBF: write bf16 hi/lo outputs (Ch/Cl) instead of fp32 Cf.
template <int K, int NO, bool RELU, bool ADDRES, bool OBF>
__global__ void __launch_bounds__(256)
k_gemmT(const __nv_bfloat16* __restrict__ Ah, const __nv_bfloat16* __restrict__ Al,
        const __nv_bfloat16* __restrict__ Wh, const __nv_bfloat16* __restrict__ Wl,
        const float* __restrict__ bias, const float* __restrict__ res,
        float* __restrict__ Cf, __nv_bfloat16* __restrict__ Ch, __nv_bfloat16* __restrict__ Cl,
        int M) {
    constexpr int BK = 64;
    constexpr int KS = K / BK;
    extern __shared__ __align__(16) unsigned char smem[];   // 2 stages x 4 arrays x 16KB
    uint32_t sb = (uint32_t)__cvta_generic_to_shared(smem);

    const int tid = threadIdx.x;
    const int m0 = blockIdx.x * 128;
    const int n0 = blockIdx.y * 128;
    const int warp = tid >> 5, lane = tid & 31;
    const int wm = warp >> 1, wn = warp & 1;   // 4 m-warps x 2 n-warps

    auto issue_stage = [&](int s) {
        int stage = s & 1;
        int kb = s * BK;
#pragma unroll
        for (int a = 0; a < 4; a++) {
            const __nv_bfloat16* S = (a == 0) ? Ah : (a == 1) ? Al : (a == 2) ? Wh : Wl;
#pragma unroll
            for (int j = 0; j < 4; j++) {
                int chunk = tid + j * 256;
                int row = chunk >> 3, cq = chunk & 7;
                uint32_t off = (uint32_t)(stage * 65536 + a * 16384 + SWZ(row * 128 + cq * 16));
                if (a < 2) {
                    int m = m0 + row;
                    if (m < M) cpa16(sb + off, S + (size_t)m * K + kb + cq * 8);
                    else { uint4 zz = make_uint4(0, 0, 0, 0); *(uint4*)(smem + off) = zz; }
                } else {
                    cpa16(sb + off, S + (size_t)(n0 + row) * K + kb + cq * 8);
                }
            }
        }
        asm volatile("cp.async.commit_group;");
    };

    float c[2][8][4];
#pragma unroll
    for (int mi = 0; mi < 2; mi++)
#pragma unroll
        for (int nb = 0; nb < 8; nb++)
#pragma unroll
            for (int q = 0; q < 4; q++) c[mi][nb][q] = 0.f;

    issue_stage(0);

    const int id = lane >> 3, r8 = lane & 7;
#pragma unroll 1
    for (int s = 0; s < KS; s++) {
        if (s + 1 < KS) {
            issue_stage(s + 1);
            asm volatile("cp.async.wait_group 1;");
        } else {
            asm volatile("cp.async.wait_group 0;");
        }
        __syncthreads();

        uint32_t sbase = sb + (uint32_t)((s & 1) * 65536);
#pragma unroll
        for (int kk = 0; kk < 4; kk++) {
            uint32_t ah_[2][4], al_[2][4];
#pragma unroll
            for (int mi = 0; mi < 2; mi++) {
                int mrow = wm * 32 + mi * 16 + (id & 1) * 8 + r8;
                uint32_t off = (uint32_t)SWZ(mrow * 128 + kk * 32 + (id >> 1) * 16);
                ldsm4(ah_[mi], sbase + off);
                ldsm4(al_[mi], sbase + 16384 + off);
            }
#pragma unroll
            for (int np = 0; np < 4; np++) {
                int nrow = wn * 64 + np * 16 + (id >> 1) * 8 + r8;
                uint32_t woff = (uint32_t)SWZ(nrow * 128 + kk * 32 + (id & 1) * 16);
                uint32_t wh_[4], wl_[4];
                ldsm4(wh_, sbase + 32768 + woff);
                ldsm4(wl_, sbase + 49152 + woff);
#pragma unroll
                for (int mi = 0; mi < 2; mi++) {
                    mma16816(c[mi][np * 2],     ah_[mi], wh_);
                    mma16816(c[mi][np * 2 + 1], ah_[mi], wh_ + 2);
                    mma16816(c[mi][np * 2],     al_[mi], wh_);
                    mma16816(c[mi][np * 2 + 1], al_[mi], wh_ + 2);
                    mma16816(c[mi][np * 2],     ah_[mi], wl_);
                    mma16816(c[mi][np * 2 + 1], ah_[mi], wl_ + 2);
                }
            }
        }
        __syncthreads();
    }

    // ---- epilogue ----
#pragma unroll
    for (int mi = 0; mi < 2; mi++) {
        int r0 = m0 + wm * 32 + mi * 16 + (lane >> 2);
#pragma unroll
        for (int nb = 0; nb < 8; nb++) {
            int col = n0 + wn * 64 + nb * 8 + (lane & 3) * 2;
            float b0 = bias[col], b1 = bias[col + 1];
            float* cc = c[mi][nb];
#pragma unroll
            for (int half = 0; half < 2; half++) {
                int r = r0 + half * 8;
                if (r >= M) continue;
                float o0 = cc[2 * half] + b0, o1 = cc[2 * half + 1] + b1;
                if (RELU) { o0 = fmaxf(o0, 0.f); o1 = fmaxf(o1, 0.f); }
                if (ADDRES) {
                    float2 rv = *(const float2*)(res + (size_t)r * NO + col);
                    o0 += rv.x; o1 += rv.y;
                }
                if (OBF) {
                    float h0 = __bfloat162float(__float2bfloat16(o0));
                    float h1 = __bfloat162float(__float2bfloat16(o1));
                    *(uint32_t*)(Ch + (size_t)r * NO + col) = bf2pack(o0, o1);
                    *(uint32_t*)(Cl + (size_t)r * NO + col) = bf2pack(o0 - h0, o1 - h1);
                } else {
                    *(float2*)(Cf + (size_t)r * NO + col) = make_float2(o0, o1);
                }
            }
        }
    }
}

static constexpr int SM_T = 131072;   // 2 stages x 4 arrays x 16KB

// ------------------- batchnorm pieces -------------------
__global__ void k_stats(const float* __restrict__ z, float* cs, float* cq) {
    int c = threadIdx.x;
    float s = 0.f, s2 = 0.f;
    for (int n = blockIdx.x; n < NN; n += gridDim.x) {
        float v = z[(size_t)n * HH + c];
        s += v;
        s2 += v * v;
    }
    atomicAdd(&cs[c], s);
    atomicAdd(&cq[c], s2);
}

// compute mu/rs and re-zero cs/cq for the next stats pass
__global__ void k_murs(float* cs, float* cq, float* mu, float* rs) {
    int c = threadIdx.x;
    float m = cs[c] * (1.0f / NN);
    mu[c] = m;
    float v = cq[c] * (1.0f / NN) - m * m;
    rs[c] = rsqrtf(v + 1e-5f);
    cs[c] = 0.f;
    cq[c] = 0.f;
}

// h += relu(bn(z));  also emit bf16 hi/lo of new h
__global__ void k_bn_relu_res_split(const float* __restrict__ z, const float* __restrict__ mu,
                                    const float* __restrict__ rs, const float* __restrict__ g,
                                    const float* __restrict__ b, float* __restrict__ h,
                                    __nv_bfloat16* __restrict__ ah, __nv_bfloat16* __restrict__ al) {
    int idx = blockIdx.x * blockDim.x + threadIdx.x;    // over NN*32 float4s
    if (idx >= NN * 32) return;
    int n = idx >> 5, c4 = (idx & 31) * 4;
    float4 z4 = *(const float4*)(z + (size_t)n * HH + c4);
    float4 h4 = *(const float4*)(h + (size_t)n * HH + c4);
    float o0 = h4.x + fmaxf((z4.x - mu[c4]) * rs[c4] * g[c4] + b[c4], 0.f);
    float o1 = h4.y + fmaxf((z4.y - mu[c4 + 1]) * rs[c4 + 1] * g[c4 + 1] + b[c4 + 1], 0.f);
    float o2 = h4.z + fmaxf((z4.z - mu[c4 + 2]) * rs[c4 + 2] * g[c4 + 2] + b[c4 + 2], 0.f);
    float o3 = h4.w + fmaxf((z4.w - mu[c4 + 3]) * rs[c4 + 3] * g[c4 + 3] + b[c4 + 3], 0.f);
    *(float4*)(h + (size_t)n * HH + c4) = make_float4(o0, o1, o2, o3);
    float p0 = __bfloat162float(__float2bfloat16(o0));
    float p1 = __bfloat162float(__float2bfloat16(o1));
    float p2 = __bfloat162float(__float2bfloat16(o2));
    float p3 = __bfloat162float(__float2bfloat16(o3));
    uint2 hi, lo;
    hi.x = bf2pack(o0, o1); hi.y = bf2pack(o2, o3);
    lo.x = bf2pack(o0 - p0, o1 - p1); lo.y = bf2pack(o2 - p2, o3 - p3);
    *(uint2*)(ah + (size_t)n * HH + c4) = hi;
    *(uint2*)(al + (size_t)n * HH + c4) = lo;
}

__global__ void k_bn(const float* __restrict__ z, const float* __restrict__ mu,
                     const float* __restrict__ rs, const float* __restrict__ g,
                     const float* __restrict__ b, float* h) {
    int idx = blockIdx.x * blockDim.x + threadIdx.x;
    if (idx >= NN * HH) return;
    int c = idx & 127;
    h[idx] = (z[idx] - mu[c]) * rs[c] * g[c] + b[c];
}

// ------------------- pooling + head -------------------
__global__ void k_zero_gsum(float* gs) {
    int i = blockIdx.x * blockDim.x + threadIdx.x;
    if (i < GG * HH) gs[i] = 0.f;
}

__global__ void k_pool(const float* __restrict__ h, const int* __restrict__ batch,
                       float* gsum) {
    int c = threadIdx.x;
    int R = (NN + gridDim.x - 1) / gridDim.x;
    int n0 = blockIdx.x * R;
    int n1 = min(n0 + R, NN);
    if (n0 >= n1) return;
    float acc = 0.f;
    int cg = batch[n0];
    for (int n = n0; n < n1; n++) {
        int g = batch[n];
        if (g != cg) {
            atomicAdd(&gsum[cg * HH + c], acc);
            acc = 0.f;
            cg = g;
        }
        acc += h[(size_t)n * HH + c];
    }
    atomicAdd(&gsum[cg * HH + c], acc);
}

__global__ void k_head(const float* __restrict__ gsum, const float* __restrict__ cnt,
                       const float* __restrict__ w1, const float* __restrict__ b1,
                       const float* __restrict__ w2, const float* __restrict__ b2,
                       float* out) {
    __shared__ float gv[HH];
    __shared__ float hid[HH];
    int t = threadIdx.x;
    int gI = blockIdx.x;
    gv[t] = gsum[gI * HH + t] / fmaxf(cnt[gI], 1.0f);
    __syncthreads();
    float s = b1[t];
#pragma unroll 8
    for (int k = 0; k < HH; k++) s += gv[k] * w1[k * HH + t];
    hid[t] = fmaxf(s, 0.f);
    __syncthreads();
    if (t < OUTN) {
        float o = b2[t];
#pragma unroll 8
        for (int k = 0; k < HH; k++) o += hid[k] * w2[k * OUTN + t];
        out[gI * OUTN + t] = o;
    }
}

// ------------------- launcher -------------------
static inline int cdiv(long a, long b) { return (int)((a + b - 1) / b); }

extern "C" void kernel_launch(void* const* d_in, const int* in_sizes, int n_in,
                              void* d_out, int out_size) {
    const void *edge_raw, *batch_raw;
    const float *emb, *pe_w, *pe_b, *proj_w, *proj_b;
    const float *gin_w1, *gin_b1, *gin_w2, *gin_b2, *bn_g, *bn_b;
    const float *ffn_w1, *ffn_b1, *ffn_w2, *ffn_b2, *fbn_g, *fbn_b;
    const float *ow1, *ob1, *ow2, *ob2;

    if (in_sizes[1] == 2 * EE) {
        edge_raw  = d_in[1];  batch_raw = d_in[2];
        emb  = (const float*)d_in[3];  pe_w = (const float*)d_in[4];  pe_b = (const float*)d_in[5];
        proj_w = (const float*)d_in[6]; proj_b = (const float*)d_in[7];
        gin_w1 = (const float*)d_in[8]; gin_b1 = (const float*)d_in[9];
        gin_w2 = (const float*)d_in[10]; gin_b2 = (const float*)d_in[11];
        bn_g = (const float*)d_in[12]; bn_b = (const float*)d_in[13];
        ffn_w1 = (const float*)d_in[14]; ffn_b1 = (const float*)d_in[15];
        ffn_w2 = (const float*)d_in[16]; ffn_b2 = (const float*)d_in[17];
        fbn_g = (const float*)d_in[18]; fbn_b = (const float*)d_in[19];
        ow1 = (const float*)d_in[20]; ob1 = (const float*)d_in[21];
        ow2 = (const float*)d_in[22]; ob2 = (const float*)d_in[23];
    } else {
        batch_raw = d_in[0];
        bn_b = (const float*)d_in[1]; bn_g = (const float*)d_in[2];
        edge_raw = d_in[3];
        emb = (const float*)d_in[4];
        ffn_b1 = (const float*)d_in[5]; ffn_b2 = (const float*)d_in[6];
        fbn_b = (const float*)d_in[7]; fbn_g = (const float*)d_in[8];
        ffn_w1 = (const float*)d_in[9]; ffn_w2 = (const float*)d_in[10];
        gin_b1 = (const float*)d_in[11]; gin_b2 = (const float*)d_in[12];
        gin_w1 = (const float*)d_in[13]; gin_w2 = (const float*)d_in[14];
        ob1 = (const float*)d_in[15]; ob2 = (const float*)d_in[16];
        ow1 = (const float*)d_in[17]; ow2 = (const float*)d_in[18];
        pe_b = (const float*)d_in[19]; pe_w = (const float*)d_in[20];
        proj_b = (const float*)d_in[21]; proj_w = (const float*)d_in[22];
    }
    float* out = (float*)d_out;

    float *h, *z, *rw, *p, *q0, *q1, *dinv, *deg, *cnt, *pe, *base;
    float *cs, *cq, *mu, *rs, *gsum;
    int *edge, *batch, *flag, *ideg, *ptr, *fill, *aux, *crow;
    __nv_bfloat16 *ah, *al, *bh, *bl, *wh, *wl;
    cudaGetSymbolAddress((void**)&h, g_h);
    cudaGetSymbolAddress((void**)&z, g_z);
    cudaGetSymbolAddress((void**)&rw, g_rw);
    cudaGetSymbolAddress((void**)&p, g_p);
    cudaGetSymbolAddress((void**)&q0, g_q0);
    cudaGetSymbolAddress((void**)&q1, g_q1);
    cudaGetSymbolAddress((void**)&dinv, g_dinv);
    cudaGetSymbolAddress((void**)&deg, g_deg);
    cudaGetSymbolAddress((void**)&cnt, g_cnt);
    cudaGetSymbolAddress((void**)&pe, g_pe);
    cudaGetSymbolAddress((void**)&base, g_base);
    cudaGetSymbolAddress((void**)&cs, g_cs);
    cudaGetSymbolAddress((void**)&cq, g_cq);
    cudaGetSymbolAddress((void**)&mu, g_mu);
    cudaGetSymbolAddress((void**)&rs, g_rs);
    cudaGetSymbolAddress((void**)&gsum, g_gsum);
    cudaGetSymbolAddress((void**)&edge, g_edge);
    cudaGetSymbolAddress((void**)&batch, g_batch);
    cudaGetSymbolAddress((void**)&flag, g_flag);
    cudaGetSymbolAddress((void**)&ideg, g_ideg);
    cudaGetSymbolAddress((void**)&ptr, g_ptr);
    cudaGetSymbolAddress((void**)&fill, g_fill);
    cudaGetSymbolAddress((void**)&aux, g_aux);
    cudaGetSymbolAddress((void**)&crow, g_crow);
    cudaGetSymbolAddress((void**)&ah, g_ah);
    cudaGetSymbolAddress((void**)&al, g_al);
    cudaGetSymbolAddress((void**)&bh, g_bh);
    cudaGetSymbolAddress((void**)&bl, g_bl);
    cudaGetSymbolAddress((void**)&wh, g_wh);
    cudaGetSymbolAddress((void**)&wl, g_wl);

    const int NT = 256;

    k_detect<<<1, 32>>>((const int*)edge_raw, flag);
    k_cvt<<<cdiv(2 * (long)EE, NT), NT>>>(edge_raw, 2 * EE, flag, edge);
    k_cvt<<<cdiv(NN, NT), NT>>>(batch_raw, NN, flag, batch);
    const int* row0 = edge;
    const int* col0 = edge + EE;

    cudaFuncSetAttribute(k_gemmT<128, 128, true,  false, true >, cudaFuncAttributeMaxDynamicSharedMemorySize, SM_T);
    cudaFuncSetAttribute(k_gemmT<128, 128, false, false, false>, cudaFuncAttributeMaxDynamicSharedMemorySize, SM_T);
    cudaFuncSetAttribute(k_gemmT<128, 256, true,  false, true >, cudaFuncAttributeMaxDynamicSharedMemorySize, SM_T);
    cudaFuncSetAttribute(k_gemmT<256, 128, false, true,  false>, cudaFuncAttributeMaxDynamicSharedMemorySize, SM_T);

    // split + transpose all layer weights (once)
    k_wsplit_all<<<cdiv(5 * 98304, NT), NT>>>(gin_w1, gin_w2, ffn_w1, ffn_w2, wh, wl);

    // degrees / CSR / counts
    k_init<<<cdiv(NN, NT), NT>>>(deg, cnt, ideg, cs, cq);
    k_deg_scatter<<<cdiv(EE, NT), NT>>>(col0, deg, ideg);
    const int NB = cdiv(NN, 256);   // 391
    k_scanA<<<NB, 256>>>(ideg, ptr, aux);
    k_scanB<<<1, 512>>>(aux, NB);
    k_scanC<<<NB, 256>>>(ptr, aux, fill);
    k_csrfill<<<cdiv(EE, NT), NT>>>(row0, col0, fill, crow);
    k_cnt_scatter<<<cdiv(NN, NT), NT>>>(batch, cnt);
    k_dinv<<<cdiv(NN, NT), NT>>>(dinv, deg);
    k_prob<<<cdiv(NN, NT), NT>>>(batch, cnt, dinv, p, q0);

    // random walk PE — fused CSR-gather step (no atomics)
    {
        float *qa = q0, *qb = q1;
        for (int k = 0; k < WALKN; k++) {
            k_rwstep<<<cdiv(NN, NT), NT>>>(ptr, crow, dinv, p, qa, qb, rw + (long)k * NN,
                                           (k < WALKN - 1) ? 1 : 0);
            float* tw = qa; qa = qb; qb = tw;
        }
    }
    k_pe<<<cdiv(NN, 256), 256>>>(rw, pe_w, pe_b, pe);

    k_base<<<1, HH>>>(emb, proj_w, proj_b, base);
    k_h0<<<cdiv((long)NN * HH, NT), NT>>>(pe, proj_w, base, h);

    const int MT = cdiv(NN, 128);            // 782 m-tiles
    const int GW = cdiv((long)NN * 32, NT);  // gather grid
    const int B4 = cdiv((long)NN * 32, NT);  // bn split grid (float4 units)
    for (int i = 0; i < LL; i++) {
        const __nv_bfloat16* whL = wh + i * 98304;
        const __nv_bfloat16* wlL = wl + i * 98304;
        k_gather<<<GW, NT>>>(ptr, crow, h, ah, al);
        k_gemmT<128, 128, true,  false, true ><<<dim3(MT, 1), 256, SM_T>>>(ah, al, whL, wlL, gin_b1 + i * HH, nullptr, nullptr, bh, bl, NN);
        k_gemmT<128, 128, false, false, false><<<dim3(MT, 1), 256, SM_T>>>(bh, bl, whL + 16384, wlL + 16384, gin_b2 + i * HH, nullptr, z, nullptr, nullptr, NN);
        k_stats<<<512, HH>>>(z, cs, cq);
        k_murs<<<1, HH>>>(cs, cq, mu, rs);
        k_bn_relu_res_split<<<B4, NT>>>(z, mu, rs, bn_g + i * HH, bn_b + i * HH, h, ah, al);

        k_gemmT<128, 256, true,  false, true ><<<dim3(MT, 2), 256, SM_T>>>(ah, al, whL + 32768, wlL + 32768, ffn_b1 + i * 2 * HH, nullptr, nullptr, bh, bl, NN);
        k_gemmT<256, 128, false, true,  false><<<dim3(MT, 1), 256, SM_T>>>(bh, bl, whL + 65536, wlL + 65536, ffn_b2 + i * HH, h, z, nullptr, nullptr, NN);
        k_stats<<<512, HH>>>(z, cs, cq);
        k_murs<<<1, HH>>>(cs, cq, mu, rs);
        k_bn<<<cdiv(NN * HH, NT), NT>>>(z, mu, rs, fbn_g + i * HH, fbn_b + i * HH, h);
    }

    k_zero_gsum<<<cdiv(GG * HH, NT), NT>>>(gsum);
    k_pool<<<512, HH>>>(h, batch, gsum);
    k_head<<<GG, HH>>>(gsum, cnt, ow1, ob1, ow2, ob2, out);
}

// round 16
// speedup vs baseline: 1.2470x; 1.0862x over previous
#include <cuda_runtime.h>
#include <cuda_bf16.h>
#include <cstdint>
#include <cstddef>

#define NN 100000
#define EE 1600000
#define GG 128
#define HH 128
#define WALKN 16
#define PEDN 16
#define LL 5
#define OUTN 10

#define SWZ(o) ((o) ^ (((o) >> 3) & 0x70))

// ------------------- scratch (device globals: no allocs allowed) -------------------
__device__ __align__(16) float g_h[NN * HH];
__device__ __align__(16) float g_z[NN * HH];
__device__ __align__(16) __nv_bfloat16 g_ah[NN * 128];
__device__ __align__(16) __nv_bfloat16 g_al[NN * 128];
__device__ __align__(16) __nv_bfloat16 g_bh[NN * 256];
__device__ __align__(16) __nv_bfloat16 g_bl[NN * 256];
__device__ __align__(16) __nv_bfloat16 g_wh[5 * 98304];
__device__ __align__(16) __nv_bfloat16 g_wl[5 * 98304];
__device__ float g_rw[WALKN * NN];
__device__ float g_p[NN];
__device__ float g_q0[NN];
__device__ float g_q1[NN];
__device__ float g_dinv[NN];
__device__ float g_deg[NN];
__device__ float g_cnt[GG];
__device__ float g_pe[NN * PEDN];
__device__ float g_base[HH];
__device__ float g_cs[HH];
__device__ float g_cq[HH];
__device__ float g_mu[HH];
__device__ float g_rs[HH];
__device__ float g_gsum[GG * HH];
__device__ int   g_edge[2 * EE];
__device__ int   g_batch[NN];
__device__ int   g_flag[1];
// CSR (by destination col)
__device__ int   g_ideg[NN];
__device__ int   g_ptr[NN + 1];
__device__ int   g_fill[NN];
__device__ int   g_aux[512];
__device__ int   g_crow[EE];

// ------------------- dtype detection / conversion -------------------
__global__ void k_detect(const int* __restrict__ e, int* flag) {
    if (threadIdx.x == 0) {
        int nz = 0;
        for (int i = 0; i < 256; i++) nz |= e[2 * i + 1];
        flag[0] = (nz == 0) ? 1 : 0;
    }
}

__global__ void k_cvt(const void* __restrict__ src, int n, const int* __restrict__ flag,
                      int* __restrict__ dst) {
    int i = blockIdx.x * blockDim.x + threadIdx.x;
    if (i >= n) return;
    if (flag[0]) dst[i] = (int)((const long long*)src)[i];
    else         dst[i] = ((const int*)src)[i];
}

// ------------------- small kernels -------------------
__global__ void k_init(float* deg, float* cnt, int* ideg, float* cs, float* cq, float* gsum) {
    int i = blockIdx.x * blockDim.x + threadIdx.x;
    if (i < NN) { deg[i] = 1.0f; ideg[i] = 0; }
    if (i < GG) cnt[i] = 0.0f;
    if (i < HH) { cs[i] = 0.f; cq[i] = 0.f; }
    if (i < GG * HH) gsum[i] = 0.f;
}

__global__ void k_deg_scatter(const int* __restrict__ col, float* deg, int* ideg) {
    int e = blockIdx.x * blockDim.x + threadIdx.x;
    if (e < EE) {
        int c = col[e];
        atomicAdd(&deg[c], 1.0f);
        atomicAdd(&ideg[c], 1);
    }
}

// ---- prefix sum over ideg -> ptr (exclusive) ----
__global__ void k_scanA(const int* __restrict__ ideg, int* ptr, int* aux) {
    __shared__ int s[256];
    int i = blockIdx.x * 256 + threadIdx.x;
    int v = (i < NN) ? ideg[i] : 0;
    s[threadIdx.x] = v;
    __syncthreads();
    for (int off = 1; off < 256; off <<= 1) {
        int t = (threadIdx.x >= off) ? s[threadIdx.x - off] : 0;
        __syncthreads();
        s[threadIdx.x] += t;
        __syncthreads();
    }
    if (i < NN) ptr[i] = s[threadIdx.x] - v;
    if (threadIdx.x == 255) aux[blockIdx.x] = s[255];
}

__global__ void k_scanB(int* aux, int nb) {
    __shared__ int s[512];
    int v = (threadIdx.x < nb) ? aux[threadIdx.x] : 0;
    s[threadIdx.x] = v;
    __syncthreads();
    for (int off = 1; off < 512; off <<= 1) {
        int t = (threadIdx.x >= off) ? s[threadIdx.x - off] : 0;
        __syncthreads();
        s[threadIdx.x] += t;
        __syncthreads();
    }
    if (threadIdx.x < nb) aux[threadIdx.x] = s[threadIdx.x] - v;
}

__global__ void k_scanC(int* ptr, const int* __restrict__ aux, int* fill) {
    int i = blockIdx.x * blockDim.x + threadIdx.x;
    if (i < NN) {
        int v = ptr[i] + aux[i >> 8];
        ptr[i] = v;
        fill[i] = v;
    }
    if (i == 0) ptr[NN] = EE;
}

__global__ void k_csrfill(const int* __restrict__ row, const int* __restrict__ col,
                          int* fill, int* crow) {
    int e = blockIdx.x * blockDim.x + threadIdx.x;
    if (e >= EE) return;
    int pos = atomicAdd(&fill[col[e]], 1);
    crow[pos] = row[e];
}

__global__ void k_cnt_scatter(const int* __restrict__ batch, float* cnt) {
    int n = blockIdx.x * blockDim.x + threadIdx.x;
    if (n < NN) atomicAdd(&cnt[batch[n]], 1.0f);
}

// dinv = rsqrt(deg); p0 = 1/cnt[batch]; q0 = p0 * dinv   (fused)
__global__ void k_prob(const int* __restrict__ batch, const float* __restrict__ cnt,
                       const float* __restrict__ deg, float* dinv, float* p, float* q) {
    int n = blockIdx.x * blockDim.x + threadIdx.x;
    if (n < NN) {
        float d = rsqrtf(deg[n]);
        dinv[n] = d;
        float v = 1.0f / fmaxf(cnt[batch[n]], 1.0f);
        p[n] = v;
        q[n] = v * d;
    }
}

// fused RW step: rw[k]=p; p = 0.9*(dinv*(sum q_old[crow]) + p*dinv^2) + 0.1*p; q_new = p*dinv
__global__ void k_rwstep(const int* __restrict__ ptr, const int* __restrict__ crow,
                         const float* __restrict__ dinv,
                         float* __restrict__ p, const float* __restrict__ qold,
                         float* __restrict__ qnew, float* __restrict__ rwk, int do_update) {
    int n = blockIdx.x * blockDim.x + threadIdx.x;
    if (n >= NN) return;
    float pn = p[n];
    rwk[n] = pn;
    if (!do_update) return;
    int e0 = __ldg(ptr + n), e1 = __ldg(ptr + n + 1);
    float s = 0.f;
    int e = e0;
    for (; e + 4 <= e1; e += 4) {
        int r0 = __ldg(crow + e), r1 = __ldg(crow + e + 1);
        int r2 = __ldg(crow + e + 2), r3 = __ldg(crow + e + 3);
        s += __ldg(qold + r0) + __ldg(qold + r1) + __ldg(qold + r2) + __ldg(qold + r3);
    }
    for (; e < e1; e++) s += __ldg(qold + __ldg(crow + e));
    float d = dinv[n];
    float pnew = 0.9f * (d * s + pn * d * d) + 0.1f * pn;
    p[n] = pnew;
    qnew[n] = pnew * d;
}

__global__ void k_pe(const float* __restrict__ rw, const float* __restrict__ pe_w,
                     const float* __restrict__ pe_b, float* pe) {
    __shared__ float sw[WALKN * PEDN];
    __shared__ float sb[PEDN];
    if (threadIdx.x < WALKN * PEDN) sw[threadIdx.x] = pe_w[threadIdx.x];
    if (threadIdx.x < PEDN) sb[threadIdx.x] = pe_b[threadIdx.x];
    __syncthreads();
    int n = blockIdx.x * blockDim.x + threadIdx.x;
    if (n >= NN) return;
    float acc[PEDN];
#pragma unroll
    for (int j = 0; j < PEDN; j++) acc[j] = sb[j];
#pragma unroll
    for (int k = 0; k < WALKN; k++) {
        float r = rw[k * NN + n];
#pragma unroll
        for (int j = 0; j < PEDN; j++) acc[j] += r * sw[k * PEDN + j];
    }
#pragma unroll
    for (int j = 0; j < PEDN; j++) pe[n * PEDN + j] = acc[j];
}

__global__ void k_base(const float* __restrict__ emb, const float* __restrict__ proj_w,
                       const float* __restrict__ proj_b, float* base) {
    int o = threadIdx.x;
    float s = proj_b[o];
#pragma unroll 8
    for (int d = 0; d < 128; d++) s += emb[d] * proj_w[d * HH + o];
    base[o] = s;
}

__global__ void k_h0(const float* __restrict__ pe, const float* __restrict__ proj_w,
                     const float* __restrict__ base, float* h) {
    int idx = blockIdx.x * blockDim.x + threadIdx.x;
    if (idx >= NN * HH) return;
    int n = idx >> 7;
    int o = idx & 127;
    float s = base[o];
    const float* pw = proj_w + 128 * HH;
#pragma unroll
    for (int j = 0; j < PEDN; j++) s += pe[n * PEDN + j] * pw[j * HH + o];
    h[idx] = s;
}

// ------------------- CSR gather + fused bf16 split (agg = h[n] + sum_in h[r]) -------------------
__device__ __forceinline__ uint32_t bf2pack(float a, float b) {
    __nv_bfloat162 v = __halves2bfloat162(__float2bfloat16(a), __float2bfloat16(b));
    return *(uint32_t*)&v;
}

__global__ void __launch_bounds__(256)
k_gather(const int* __restrict__ ptr, const int* __restrict__ crow,
         const float* __restrict__ h,
         __nv_bfloat16* __restrict__ ah, __nv_bfloat16* __restrict__ al) {
    int w = (blockIdx.x * blockDim.x + threadIdx.x) >> 5;
    if (w >= NN) return;
    int lane = threadIdx.x & 31;
    float4 acc = __ldg((const float4*)(h + (size_t)w * HH) + lane);
    int e0 = __ldg(ptr + w), e1 = __ldg(ptr + w + 1);
    int e = e0;
    for (; e + 4 <= e1; e += 4) {
        int r0 = __ldg(crow + e), r1 = __ldg(crow + e + 1);
        int r2 = __ldg(crow + e + 2), r3 = __ldg(crow + e + 3);
        float4 v0 = __ldg((const float4*)(h + (size_t)r0 * HH) + lane);
        float4 v1 = __ldg((const float4*)(h + (size_t)r1 * HH) + lane);
        float4 v2 = __ldg((const float4*)(h + (size_t)r2 * HH) + lane);
        float4 v3 = __ldg((const float4*)(h + (size_t)r3 * HH) + lane);
        acc.x += v0.x + v1.x + v2.x + v3.x;
        acc.y += v0.y + v1.y + v2.y + v3.y;
        acc.z += v0.z + v1.z + v2.z + v3.z;
        acc.w += v0.w + v1.w + v2.w + v3.w;
    }
    for (; e < e1; e++) {
        int r = __ldg(crow + e);
        float4 v = __ldg((const float4*)(h + (size_t)r * HH) + lane);
        acc.x += v.x; acc.y += v.y; acc.z += v.z; acc.w += v.w;
    }
    float hx = __bfloat162float(__float2bfloat16(acc.x));
    float hy = __bfloat162float(__float2bfloat16(acc.y));
    float hz = __bfloat162float(__float2bfloat16(acc.z));
    float hw = __bfloat162float(__float2bfloat16(acc.w));
    uint2 hi, lo;
    hi.x = bf2pack(acc.x, acc.y);
    hi.y = bf2pack(acc.z, acc.w);
    lo.x = bf2pack(acc.x - hx, acc.y - hy);
    lo.y = bf2pack(acc.z - hz, acc.w - hw);
    *(uint2*)(ah + (size_t)w * HH + lane * 4) = hi;
    *(uint2*)(al + (size_t)w * HH + lane * 4) = lo;
}

// split + transpose ALL layer weights into [NO][K] bf16 hi/lo
__global__ void k_wsplit_all(const float* __restrict__ g1, const float* __restrict__ g2,
                             const float* __restrict__ f1, const float* __restrict__ f2,
                             __nv_bfloat16* __restrict__ wh, __nv_bfloat16* __restrict__ wl) {
    int idx = blockIdx.x * blockDim.x + threadIdx.x;
    if (idx >= 5 * 98304) return;
    int layer = idx / 98304, r = idx % 98304;
    const float* W; int Kd, NOd, base;
    if (r < 16384)      { W = g1 + layer * 16384; Kd = 128; NOd = 128; base = layer * 98304; }
    else if (r < 32768) { W = g2 + layer * 16384; r -= 16384; Kd = 128; NOd = 128; base = layer * 98304 + 16384; }
    else if (r < 65536) { W = f1 + layer * 32768; r -= 32768; Kd = 128; NOd = 256; base = layer * 98304 + 32768; }
    else                { W = f2 + layer * 32768; r -= 65536; Kd = 256; NOd = 128; base = layer * 98304 + 65536; }
    int k = r / NOd, n = r % NOd;
    float x = W[r];
    __nv_bfloat16 h = __float2bfloat16(x);
    wh[base + n * Kd + k] = h;
    wl[base + n * Kd + k] = __float2bfloat16(x - __bfloat162float(h));
}

// ------------------- bf16x3 tensor-core GEMM -------------------
__device__ __forceinline__ void ldsm4(uint32_t* r, uint32_t addr) {
    asm volatile("ldmatrix.sync.aligned.m8n8.x4.shared.b16 {%0,%1,%2,%3}, [%4];"
                 : "=r"(r[0]), "=r"(r[1]), "=r"(r[2]), "=r"(r[3]) : "r"(addr));
}

__device__ __forceinline__ void mma16816(float* c, const uint32_t* a, const uint32_t* b) {
    asm volatile("mma.sync.aligned.m16n8k16.row.col.f32.bf16.bf16.f32 "
                 "{%0,%1,%2,%3}, {%4,%5,%6,%7}, {%8,%9}, {%0,%1,%2,%3};"
                 : "+f"(c[0]), "+f"(c[1]), "+f"(c[2]), "+f"(c[3])
                 : "r"(a[0]), "r"(a[1]), "r"(a[2]), "r"(a[3]), "r"(b[0]), "r"(b[1]));
}

__device__ __forceinline__ void cpa16(uint32_t dst, const void* src) {
    asm volatile("cp.async.cg.shared.global [%0], [%1], 16;" :: "r"(dst), "l"(src));
}

// C = A @ W via split bf16 (AhWh + AlWh + AhWl), fp32 accum. Wh/Wl transposed [NO][K].
// OBF: write bf16 hi/lo outputs. STATS: per-column sum/sumsq via shuffle + global RED.
template <int K, int NO, bool RELU, bool ADDRES, bool OBF, bool STATS>
__global__ void __launch_bounds__(256)
k_gemmT(const __nv_bfloat16* __restrict__ Ah, const __nv_bfloat16* __restrict__ Al,
        const __nv_bfloat16* __restrict__ Wh, const __nv_bfloat16* __restrict__ Wl,
        const float* __restrict__ bias, const float* __restrict__ res,
        float* __restrict__ Cf, __nv_bfloat16* __restrict__ Ch, __nv_bfloat16* __restrict__ Cl,
        float* __restrict__ cs, float* __restrict__ cq, int M) {
    constexpr int BK = 64;
    constexpr int KS = K / BK;
    extern __shared__ __align__(16) unsigned char smem[];   // 2 stages x 4 arrays x 16KB
    uint32_t sb = (uint32_t)__cvta_generic_to_shared(smem);

    const int tid = threadIdx.x;
    const int m0 = blockIdx.x * 128;
    const int n0 = blockIdx.y * 128;
    const int warp = tid >> 5, lane = tid & 31;
    const int wm = warp >> 1, wn = warp & 1;   // 4 m-warps x 2 n-warps

    auto issue_stage = [&](int s) {
        int stage = s & 1;
        int kb = s * BK;
#pragma unroll
        for (int a = 0; a < 4; a++) {
            const __nv_bfloat16* S = (a == 0) ? Ah : (a == 1) ? Al : (a == 2) ? Wh : Wl;
#pragma unroll
            for (int j = 0; j < 4; j++) {
                int chunk = tid + j * 256;
                int row = chunk >> 3, cq8 = chunk & 7;
                uint32_t off = (uint32_t)(stage * 65536 + a * 16384 + SWZ(row * 128 + cq8 * 16));
                if (a < 2) {
                    int m = m0 + row;
                    if (m < M) cpa16(sb + off, S + (size_t)m * K + kb + cq8 * 8);
                    else { uint4 zz = make_uint4(0, 0, 0, 0); *(uint4*)(smem + off) = zz; }
                } else {
                    cpa16(sb + off, S + (size_t)(n0 + row) * K + kb + cq8 * 8);
                }
            }
        }
        asm volatile("cp.async.commit_group;");
    };

    float c[2][8][4];
#pragma unroll
    for (int mi = 0; mi < 2; mi++)
#pragma unroll
        for (int nb = 0; nb < 8; nb++)
#pragma unroll
            for (int q = 0; q < 4; q++) c[mi][nb][q] = 0.f;

    issue_stage(0);

    const int id = lane >> 3, r8 = lane & 7;
#pragma unroll 1
    for (int s = 0; s < KS; s++) {
        if (s + 1 < KS) {
            issue_stage(s + 1);
            asm volatile("cp.async.wait_group 1;");
        } else {
            asm volatile("cp.async.wait_group 0;");
        }
        __syncthreads();

        uint32_t sbase = sb + (uint32_t)((s & 1) * 65536);
#pragma unroll
        for (int kk = 0; kk < 4; kk++) {
            uint32_t ah_[2][4], al_[2][4];
#pragma unroll
            for (int mi = 0; mi < 2; mi++) {
                int mrow = wm * 32 + mi * 16 + (id & 1) * 8 + r8;
                uint32_t off = (uint32_t)SWZ(mrow * 128 + kk * 32 + (id >> 1) * 16);
                ldsm4(ah_[mi], sbase + off);
                ldsm4(al_[mi], sbase + 16384 + off);
            }
#pragma unroll
            for (int np = 0; np < 4; np++) {
                int nrow = wn * 64 + np * 16 + (id >> 1) * 8 + r8;
                uint32_t woff = (uint32_t)SWZ(nrow * 128 + kk * 32 + (id & 1) * 16);
                uint32_t wh_[4], wl_[4];
                ldsm4(wh_, sbase + 32768 + woff);
                ldsm4(wl_, sbase + 49152 + woff);
#pragma unroll
                for (int mi = 0; mi < 2; mi++) {
                    mma16816(c[mi][np * 2],     ah_[mi], wh_);
                    mma16816(c[mi][np * 2 + 1], ah_[mi], wh_ + 2);
                    mma16816(c[mi][np * 2],     al_[mi], wh_);
                    mma16816(c[mi][np * 2 + 1], al_[mi], wh_ + 2);
                    mma16816(c[mi][np * 2],     ah_[mi], wl_);
                    mma16816(c[mi][np * 2 + 1], ah_[mi], wl_ + 2);
                }
            }
        }
        __syncthreads();
    }

    // ---- epilogue ----
#pragma unroll
    for (int nb = 0; nb < 8; nb++) {
        int col = n0 + wn * 64 + nb * 8 + (lane & 3) * 2;
        float b0 = bias[col], b1 = bias[col + 1];
        float ls0 = 0.f, lq0 = 0.f, ls1 = 0.f, lq1 = 0.f;
#pragma unroll
        for (int mi = 0; mi < 2; mi++) {
            int r0 = m0 + wm * 32 + mi * 16 + (lane >> 2);
            float* cc = c[mi][nb];
#pragma unroll
            for (int half = 0; half < 2; half++) {
                int r = r0 + half * 8;
                if (r >= M) continue;
                float o0 = cc[2 * half] + b0, o1 = cc[2 * half + 1] + b1;
                if (RELU) { o0 = fmaxf(o0, 0.f); o1 = fmaxf(o1, 0.f); }
                if (ADDRES) {
                    float2 rv = *(const float2*)(res + (size_t)r * NO + col);
                    o0 += rv.x; o1 += rv.y;
                }
                if (OBF) {
                    float h0 = __bfloat162float(__float2bfloat16(o0));
                    float h1 = __bfloat162float(__float2bfloat16(o1));
                    *(uint32_t*)(Ch + (size_t)r * NO + col) = bf2pack(o0, o1);
                    *(uint32_t*)(Cl + (size_t)r * NO + col) = bf2pack(o0 - h0, o1 - h1);
                } else {
                    *(float2*)(Cf + (size_t)r * NO + col) = make_float2(o0, o1);
                }
                if (STATS) {
                    ls0 += o0; lq0 += o0 * o0;
                    ls1 += o1; lq1 += o1 * o1;
                }
            }
        }
        if (STATS) {
            // reduce across the 8 lanes sharing these columns (same lane&3)
#pragma unroll
            for (int d = 4; d <= 16; d <<= 1) {
                ls0 += __shfl_xor_sync(0xffffffffu, ls0, d);
                lq0 += __shfl_xor_sync(0xffffffffu, lq0, d);
                ls1 += __shfl_xor_sync(0xffffffffu, ls1, d);
                lq1 += __shfl_xor_sync(0xffffffffu, lq1, d);
            }
            if ((lane >> 2) == 0) {   // lanes 0..3: one RED per column
                atomicAdd(&cs[col], ls0);
                atomicAdd(&cq[col], lq0);
                atomicAdd(&cs[col + 1], ls1);
                atomicAdd(&cq[col + 1], lq1);
            }
        }
    }
}

static constexpr int SM_T = 131072;   // 2 stages x 4 arrays x 16KB

// ------------------- batchnorm pieces -------------------
// compute mu/rs and re-zero cs/cq for the next stats pass
__global__ void k_murs(float* cs, float* cq, float* mu, float* rs) {
    int c = threadIdx.x;
    float m = cs[c] * (1.0f / NN);
    mu[c] = m;
    float v = cq[c] * (1.0f / NN) - m * m;
    rs[c] = rsqrtf(v + 1e-5f);
    cs[c] = 0.f;
    cq[c] = 0.f;
}

// h += relu(bn(z));  also emit bf16 hi/lo of new h
__global__ void k_bn_relu_res_split(const float* __restrict__ z, const float* __restrict__ mu,
                                    const float* __restrict__ rs, const float* __restrict__ g,
                                    const float* __restrict__ b, float* __restrict__ h,
                                    __nv_bfloat16* __restrict__ ah, __nv_bfloat16* __restrict__ al) {
    int idx = blockIdx.x * blockDim.x + threadIdx.x;    // over NN*32 float4s
    if (idx >= NN * 32) return;
    int n = idx >> 5, c4 = (idx & 31) * 4;
    float4 z4 = *(const float4*)(z + (size_t)n * HH + c4);
    float4 h4 = *(const float4*)(h + (size_t)n * HH + c4);
    float o0 = h4.x + fmaxf((z4.x - mu[c4]) * rs[c4] * g[c4] + b[c4], 0.f);
    float o1 = h4.y + fmaxf((z4.y - mu[c4 + 1]) * rs[c4 + 1] * g[c4 + 1] + b[c4 + 1], 0.f);
    float o2 = h4.z + fmaxf((z4.z - mu[c4 + 2]) * rs[c4 + 2] * g[c4 + 2] + b[c4 + 2], 0.f);
    float o3 = h4.w + fmaxf((z4.w - mu[c4 + 3]) * rs[c4 + 3] * g[c4 + 3] + b[c4 + 3], 0.f);
    *(float4*)(h + (size_t)n * HH + c4) = make_float4(o0, o1, o2, o3);
    float p0 = __bfloat162float(__float2bfloat16(o0));
    float p1 = __bfloat162float(__float2bfloat16(o1));
    float p2 = __bfloat162float(__float2bfloat16(o2));
    float p3 = __bfloat162float(__float2bfloat16(o3));
    uint2 hi, lo;
    hi.x = bf2pack(o0, o1); hi.y = bf2pack(o2, o3);
    lo.x = bf2pack(o0 - p0, o1 - p1); lo.y = bf2pack(o2 - p2, o3 - p3);
    *(uint2*)(ah + (size_t)n * HH + c4) = hi;
    *(uint2*)(al + (size_t)n * HH + c4) = lo;
}

__global__ void k_bn(const float* __restrict__ z, const float* __restrict__ mu,
                     const float* __restrict__ rs, const float* __restrict__ g,
                     const float* __restrict__ b, float* h) {
    int idx = blockIdx.x * blockDim.x + threadIdx.x;
    if (idx >= NN * HH) return;
    int c = idx & 127;
    h[idx] = (z[idx] - mu[c]) * rs[c] * g[c] + b[c];
}

// ------------------- pooling + head -------------------
__global__ void k_pool(const float* __restrict__ h, const int* __restrict__ batch,
                       float* gsum) {
    int c = threadIdx.x;
    int R = (NN + gridDim.x - 1) / gridDim.x;
    int n0 = blockIdx.x * R;
    int n1 = min(n0 + R, NN);
    if (n0 >= n1) return;
    float acc = 0.f;
    int cg = batch[n0];
    for (int n = n0; n < n1; n++) {
        int g = batch[n];
        if (g != cg) {
            atomicAdd(&gsum[cg * HH + c], acc);
            acc = 0.f;
            cg = g;
        }
        acc += h[(size_t)n * HH + c];
    }
    atomicAdd(&gsum[cg * HH + c], acc);
}

__global__ void k_head(const float* __restrict__ gsum, const float* __restrict__ cnt,
                       const float* __restrict__ w1, const float* __restrict__ b1,
                       const float* __restrict__ w2, const float* __restrict__ b2,
                       float* out) {
    __shared__ float gv[HH];
    __shared__ float hid[HH];
    int t = threadIdx.x;
    int gI = blockIdx.x;
    gv[t] = gsum[gI * HH + t] / fmaxf(cnt[gI], 1.0f);
    __syncthreads();
    float s = b1[t];
#pragma unroll 8
    for (int k = 0; k < HH; k++) s += gv[k] * w1[k * HH + t];
    hid[t] = fmaxf(s, 0.f);
    __syncthreads();
    if (t < OUTN) {
        float o = b2[t];
#pragma unroll 8
        for (int k = 0; k < HH; k++) o += hid[k] * w2[k * OUTN + t];
        out[gI * OUTN + t] = o;
    }
}

// ------------------- launcher -------------------
static inline int cdiv(long a, long b) { return (int)((a + b - 1) / b); }

extern "C" void kernel_launch(void* const* d_in, const int* in_sizes, int n_in,
                              void* d_out, int out_size) {
    const void *edge_raw, *batch_raw;
    const float *emb, *pe_w, *pe_b, *proj_w, *proj_b;
    const float *gin_w1, *gin_b1, *gin_w2, *gin_b2, *bn_g, *bn_b;
    const float *ffn_w1, *ffn_b1, *ffn_w2, *ffn_b2, *fbn_g, *fbn_b;
    const float *ow1, *ob1, *ow2, *ob2;

    if (in_sizes[1] == 2 * EE) {
        edge_raw  = d_in[1];  batch_raw = d_in[2];
        emb  = (const float*)d_in[3];  pe_w = (const float*)d_in[4];  pe_b = (const float*)d_in[5];
        proj_w = (const float*)d_in[6]; proj_b = (const float*)d_in[7];
        gin_w1 = (const float*)d_in[8]; gin_b1 = (const float*)d_in[9];
        gin_w2 = (const float*)d_in[10]; gin_b2 = (const float*)d_in[11];
        bn_g = (const float*)d_in[12]; bn_b = (const float*)d_in[13];
        ffn_w1 = (const float*)d_in[14]; ffn_b1 = (const float*)d_in[15];
        ffn_w2 = (const float*)d_in[16]; ffn_b2 = (const float*)d_in[17];
        fbn_g = (const float*)d_in[18]; fbn_b = (const float*)d_in[19];
        ow1 = (const float*)d_in[20]; ob1 = (const float*)d_in[21];
        ow2 = (const float*)d_in[22]; ob2 = (const float*)d_in[23];
    } else {
        batch_raw = d_in[0];
        bn_b = (const float*)d_in[1]; bn_g = (const float*)d_in[2];
        edge_raw = d_in[3];
        emb = (const float*)d_in[4];
        ffn_b1 = (const float*)d_in[5]; ffn_b2 = (const float*)d_in[6];
        fbn_b = (const float*)d_in[7]; fbn_g = (const float*)d_in[8];
        ffn_w1 = (const float*)d_in[9]; ffn_w2 = (const float*)d_in[10];
        gin_b1 = (const float*)d_in[11]; gin_b2 = (const float*)d_in[12];
        gin_w1 = (const float*)d_in[13]; gin_w2 = (const float*)d_in[14];
        ob1 = (const float*)d_in[15]; ob2 = (const float*)d_in[16];
        ow1 = (const float*)d_in[17]; ow2 = (const float*)d_in[18];
        pe_b = (const float*)d_in[19]; pe_w = (const float*)d_in[20];
        proj_b = (const float*)d_in[21]; proj_w = (const float*)d_in[22];
    }
    float* out = (float*)d_out;

    float *h, *z, *rw, *p, *q0, *q1, *dinv, *deg, *cnt, *pe, *base;
    float *cs, *cq, *mu, *rs, *gsum;
    int *edge, *batch, *flag, *ideg, *ptr, *fill, *aux, *crow;
    __nv_bfloat16 *ah, *al, *bh, *bl, *wh, *wl;
    cudaGetSymbolAddress((void**)&h, g_h);
    cudaGetSymbolAddress((void**)&z, g_z);
    cudaGetSymbolAddress((void**)&rw, g_rw);
    cudaGetSymbolAddress((void**)&p, g_p);
    cudaGetSymbolAddress((void**)&q0, g_q0);
    cudaGetSymbolAddress((void**)&q1, g_q1);
    cudaGetSymbolAddress((void**)&dinv, g_dinv);
    cudaGetSymbolAddress((void**)&deg, g_deg);
    cudaGetSymbolAddress((void**)&cnt, g_cnt);
    cudaGetSymbolAddress((void**)&pe, g_pe);
    cudaGetSymbolAddress((void**)&base, g_base);
    cudaGetSymbolAddress((void**)&cs, g_cs);
    cudaGetSymbolAddress((void**)&cq, g_cq);
    cudaGetSymbolAddress((void**)&mu, g_mu);
    cudaGetSymbolAddress((void**)&rs, g_rs);
    cudaGetSymbolAddress((void**)&gsum, g_gsum);
    cudaGetSymbolAddress((void**)&edge, g_edge);
    cudaGetSymbolAddress((void**)&batch, g_batch);
    cudaGetSymbolAddress((void**)&flag, g_flag);
    cudaGetSymbolAddress((void**)&ideg, g_ideg);
    cudaGetSymbolAddress((void**)&ptr, g_ptr);
    cudaGetSymbolAddress((void**)&fill, g_fill);
    cudaGetSymbolAddress((void**)&aux, g_aux);
    cudaGetSymbolAddress((void**)&crow, g_crow);
    cudaGetSymbolAddress((void**)&ah, g_ah);
    cudaGetSymbolAddress((void**)&al, g_al);
    cudaGetSymbolAddress((void**)&bh, g_bh);
    cudaGetSymbolAddress((void**)&bl, g_bl);
    cudaGetSymbolAddress((void**)&wh, g_wh);
    cudaGetSymbolAddress((void**)&wl, g_wl);

    const int NT = 256;

    k_detect<<<1, 32>>>((const int*)edge_raw, flag);
    k_cvt<<<cdiv(2 * (long)EE, NT), NT>>>(edge_raw, 2 * EE, flag, edge);
    k_cvt<<<cdiv(NN, NT), NT>>>(batch_raw, NN, flag, batch);
    const int* row0 = edge;
    const int* col0 = edge + EE;

    cudaFuncSetAttribute(k_gemmT<128, 128, true,  false, true,  false>, cudaFuncAttributeMaxDynamicSharedMemorySize, SM_T);
    cudaFuncSetAttribute(k_gemmT<128, 128, false, false, false, true >, cudaFuncAttributeMaxDynamicSharedMemorySize, SM_T);
    cudaFuncSetAttribute(k_gemmT<128, 256, true,  false, true,  false>, cudaFuncAttributeMaxDynamicSharedMemorySize, SM_T);
    cudaFuncSetAttribute(k_gemmT<256, 128, false, true,  false, true >, cudaFuncAttributeMaxDynamicSharedMemorySize, SM_T);

    // split + transpose all layer weights (once)
    k_wsplit_all<<<cdiv(5 * 98304, NT), NT>>>(gin_w1, gin_w2, ffn_w1, ffn_w2, wh, wl);

    // degrees / CSR / counts
    k_init<<<cdiv(NN, NT), NT>>>(deg, cnt, ideg, cs, cq, gsum);
    k_deg_scatter<<<cdiv(EE, NT), NT>>>(col0, deg, ideg);
    const int NB = cdiv(NN, 256);   // 391
    k_scanA<<<NB, 256>>>(ideg, ptr, aux);
    k_scanB<<<1, 512>>>(aux, NB);
    k_scanC<<<NB, 256>>>(ptr, aux, fill);
    k_csrfill<<<cdiv(EE, NT), NT>>>(row0, col0, fill, crow);
    k_cnt_scatter<<<cdiv(NN, NT), NT>>>(batch, cnt);
    k_prob<<<cdiv(NN, NT), NT>>>(batch, cnt, deg, dinv, p, q0);

    // random walk PE — fused CSR-gather step (no atomics)
    {
        float *qa = q0, *qb = q1;
        for (int k = 0; k < WALKN; k++) {
            k_rwstep<<<cdiv(NN, NT), NT>>>(ptr, crow, dinv, p, qa, qb, rw + (long)k * NN,
                                           (k < WALKN - 1) ? 1 : 0);
            float* tw = qa; qa = qb; qb = tw;
        }
    }
    k_pe<<<cdiv(NN, 256), 256>>>(rw, pe_w, pe_b, pe);

    k_base<<<1, HH>>>(emb, proj_w, proj_b, base);
    k_h0<<<cdiv((long)NN * HH, NT), NT>>>(pe, proj_w, base, h);

    const int MT = cdiv(NN, 128);            // 782 m-tiles
    const int GW = cdiv((long)NN * 32, NT);  // gather grid
    const int B4 = cdiv((long)NN * 32, NT);  // bn split grid (float4 units)
    for (int i = 0; i < LL; i++) {
        const __nv_bfloat16* whL = wh + i * 98304;
        const __nv_bfloat16* wlL = wl + i * 98304;
        k_gather<<<GW, NT>>>(ptr, crow, h, ah, al);
        k_gemmT<128, 128, true,  false, true,  false><<<dim3(MT, 1), 256, SM_T>>>(ah, al, whL, wlL, gin_b1 + i * HH, nullptr, nullptr, bh, bl, nullptr, nullptr, NN);
        k_gemmT<128, 128, false, false, false, true ><<<dim3(MT, 1), 256, SM_T>>>(bh, bl, whL + 16384, wlL + 16384, gin_b2 + i * HH, nullptr, z, nullptr, nullptr, cs, cq, NN);
        k_murs<<<1, HH>>>(cs, cq, mu, rs);
        k_bn_relu_res_split<<<B4, NT>>>(z, mu, rs, bn_g + i * HH, bn_b + i * HH, h, ah, al);

        k_gemmT<128, 256, true,  false, true,  false><<<dim3(MT, 2), 256, SM_T>>>(ah, al, whL + 32768, wlL + 32768, ffn_b1 + i * 2 * HH, nullptr, nullptr, bh, bl, nullptr, nullptr, NN);
        k_gemmT<256, 128, false, true,  false, true ><<<dim3(MT, 1), 256, SM_T>>>(bh, bl, whL + 65536, wlL + 65536, ffn_b2 + i * HH, h, z, nullptr, nullptr, cs, cq, NN);
        k_murs<<<1, HH>>>(cs, cq, mu, rs);
        k_bn<<<cdiv(NN * HH, NT), NT>>>(z, mu, rs, fbn_g + i * HH, fbn_b + i * HH, h);
    }

    k_pool<<<512, HH>>>(h, batch, gsum);
    k_head<<<GG, HH>>>(gsum, cnt, ow1, ob1, ow2, ob2, out);
}